// round 8
// baseline (speedup 1.0000x reference)
#include <cuda_runtime.h>
#include <cuda_fp16.h>
#include <math.h>
#include <stdint.h>

#define NNODES 100000
#define NEDGES 3200000
#define NF 256

// ---------------- scratch (device globals; no allocs allowed) ----------------
__device__ float g_bufA[(size_t)NNODES * NF];           // fp32 [M,256]
__device__ float g_bufB[(size_t)NNODES * NF];           // aliased as fp16 split [M,512]
__device__ __half g_Asp[(size_t)NNODES * 512];          // fp16 split [hi(256)|lo(256)]
__device__ __half g_xh[(size_t)NNODES * NF];            // fp16 [M,256] gather operand
__device__ int   g_rowptr[NNODES + 1];
__device__ int   g_cursor[NNODES];
__device__ uint2 g_cw[NEDGES];                          // packed {col, weight-bits}
__device__ __half g_Wh[3][NF * NF];                     // fp16 weights, [N][K] K-major

// ---------------- helpers ----------------
__device__ __forceinline__ uint32_t smem_u32(const void* p) {
    uint32_t a;
    asm("{ .reg .u64 t; cvta.to.shared.u64 t, %1; cvt.u32.u64 %0, t; }" : "=r"(a) : "l"(p));
    return a;
}

#define LDSM_X4(r0, r1, r2, r3, addr) \
    asm volatile("ldmatrix.sync.aligned.m8n8.x4.shared.b16 {%0,%1,%2,%3}, [%4];" \
                 : "=r"(r0), "=r"(r1), "=r"(r2), "=r"(r3) : "r"(addr))

__device__ __forceinline__ void mma_f16(float* d, const uint32_t* a, const uint32_t* b) {
    asm volatile(
        "mma.sync.aligned.m16n8k16.row.col.f32.f16.f16.f32 "
        "{%0,%1,%2,%3}, {%4,%5,%6,%7}, {%8,%9}, {%0,%1,%2,%3};"
        : "+f"(d[0]), "+f"(d[1]), "+f"(d[2]), "+f"(d[3])
        : "r"(a[0]), "r"(a[1]), "r"(a[2]), "r"(a[3]), "r"(b[0]), "r"(b[1]));
}

#define CP_ASYNC16(dst, src) \
    asm volatile("cp.async.cg.shared.global [%0], [%1], 16;" :: "r"(dst), "l"(src))
#define CP_COMMIT() asm volatile("cp.async.commit_group;")
#define CP_WAIT0() asm volatile("cp.async.wait_group 0;")

__device__ __forceinline__ void split4(const float* f, uint2& hi, uint2& lo) {
    __half h[4], l[4];
#pragma unroll
    for (int e = 0; e < 4; e++) {
        h[e] = __float2half_rn(f[e]);
        l[e] = __float2half_rn(f[e] - __half2float(h[e]));
    }
    hi = *(uint2*)h;
    lo = *(uint2*)l;
}

// ---------------- merged: x -> fp16 copy + degree histogram ----------------
__global__ void conv_hist_kernel(const float* __restrict__ x, __half* __restrict__ xh,
                                 const int* __restrict__ erow, int E, int total4) {
    int i = blockIdx.x * blockDim.x + threadIdx.x;
    if (i < total4) {
        float4 v = ((const float4*)x)[i];
        __half h[4] = {__float2half_rn(v.x), __float2half_rn(v.y),
                       __float2half_rn(v.z), __float2half_rn(v.w)};
        *(uint2*)(xh + (size_t)i * 4) = *(uint2*)h;
    }
    if (i < E) atomicAdd(&g_rowptr[erow[i]], 1);
}

__global__ void scan_kernel(int n) {
    __shared__ int part[1024];
    int t = threadIdx.x;
    int CH = (n + 1023) / 1024;
    int beg = t * CH;
    int end = min(beg + CH, n);
    int s = 0;
    for (int i = beg; i < end; i++) s += g_rowptr[i];
    part[t] = s;
    __syncthreads();
    for (int off = 1; off < 1024; off <<= 1) {
        int v = (t >= off) ? part[t - off] : 0;
        __syncthreads();
        part[t] += v;
        __syncthreads();
    }
    int base = (t == 0) ? 0 : part[t - 1];
    int run = base;
    for (int i = beg; i < end; i++) {
        int c = g_rowptr[i];
        g_rowptr[i] = run;
        g_cursor[i] = run;
        run += c;
    }
    if (t == 1023) g_rowptr[n] = part[1023];
}

// unroll x2: two independent atomic chains per thread
__global__ void scatter_kernel(const int* __restrict__ erow,
                               const int* __restrict__ ecol,
                               const float* __restrict__ ew, int E) {
    int i = (blockIdx.x * blockDim.x + threadIdx.x) * 2;
#pragma unroll
    for (int j = 0; j < 2; j++) {
        if (i + j < E) {
            int r = erow[i + j];
            int pos = atomicAdd(&g_cursor[r], 1);
            uint2 cw;
            cw.x = (uint32_t)ecol[i + j];
            cw.y = __float_as_uint(ew[i + j]);
            g_cw[pos] = cw;
        }
    }
}

// ---------------- SPMM (fp16 gather, packed edges) + residual -> fp16 split ----------------
__global__ void spmm_f16_kernel(const __half* __restrict__ src,
                                __half* __restrict__ dst, int n) {
    int gw = (blockIdx.x * blockDim.x + threadIdx.x) >> 5;
    int row = gw >> 1;
    if (row >= n) return;
    int half_ = gw & 1;
    int lane = threadIdx.x & 31;
    int f4 = half_ * 32 + lane;
    const uint2* s2 = (const uint2*)src;
    uint2 rv = s2[(size_t)row * 64 + f4];
    float2 p0 = __half22float2(*(__half2*)&rv.x);
    float2 p1 = __half22float2(*(__half2*)&rv.y);
    float ax = p0.x, ay = p0.y, az = p1.x, aw = p1.y;
    int beg = g_rowptr[row], end = g_rowptr[row + 1];
    int e = beg;
    for (; e + 4 <= end; e += 4) {
        uint2 cw0 = __ldg(&g_cw[e]),     cw1 = __ldg(&g_cw[e + 1]);
        uint2 cw2 = __ldg(&g_cw[e + 2]), cw3 = __ldg(&g_cw[e + 3]);
        float w0 = __uint_as_float(cw0.y), w1 = __uint_as_float(cw1.y);
        float w2 = __uint_as_float(cw2.y), w3 = __uint_as_float(cw3.y);
        uint2 v0 = s2[(size_t)cw0.x * 64 + f4];
        uint2 v1 = s2[(size_t)cw1.x * 64 + f4];
        uint2 v2 = s2[(size_t)cw2.x * 64 + f4];
        uint2 v3 = s2[(size_t)cw3.x * 64 + f4];
        float2 a0 = __half22float2(*(__half2*)&v0.x), b0 = __half22float2(*(__half2*)&v0.y);
        float2 a1 = __half22float2(*(__half2*)&v1.x), b1 = __half22float2(*(__half2*)&v1.y);
        float2 a2 = __half22float2(*(__half2*)&v2.x), b2 = __half22float2(*(__half2*)&v2.y);
        float2 a3 = __half22float2(*(__half2*)&v3.x), b3 = __half22float2(*(__half2*)&v3.y);
        ax += w0 * a0.x + w1 * a1.x + w2 * a2.x + w3 * a3.x;
        ay += w0 * a0.y + w1 * a1.y + w2 * a2.y + w3 * a3.y;
        az += w0 * b0.x + w1 * b1.x + w2 * b2.x + w3 * b3.x;
        aw += w0 * b0.y + w1 * b1.y + w2 * b2.y + w3 * b3.y;
    }
    for (; e < end; e++) {
        uint2 cw = __ldg(&g_cw[e]);
        float w = __uint_as_float(cw.y);
        uint2 v = s2[(size_t)cw.x * 64 + f4];
        float2 a = __half22float2(*(__half2*)&v.x), b = __half22float2(*(__half2*)&v.y);
        ax += w * a.x; ay += w * a.y; az += w * b.x; aw += w * b.y;
    }
    float res[4] = {ax, ay, az, aw};
    uint2 hi, lo;
    split4(res, hi, lo);
    *(uint2*)(dst + (size_t)row * 512 + f4 * 4) = hi;
    *(uint2*)(dst + (size_t)row * 512 + 256 + f4 * 4) = lo;
}

// ---------------- weight prep: W[K][N] fp32 -> Wh[N][K] fp16 ----------------
__global__ void prep_w_f16(const float* __restrict__ W, __half* __restrict__ Bh) {
    int n = blockIdx.x;
    int k = threadIdx.x;
    Bh[(size_t)n * NF + k] = __float2half_rn(W[(size_t)k * NF + n]);
}

// ---------------- fp16x2 GEMM: BM=64, BN=256, BK=64, 2-stage, occ=2 ----------------
// A: fp16 [M,512] (hi|lo); B: fp16 [256,256] K-major. grid=(ceil(M/64)).
// OUT: 0 -> fp32 [M,256]; 1 -> fp16 split [M,512]; 2 -> fp16 [M,256]
#define PITCH 72
#define A_SZ (64 * PITCH * 2)
#define B_SZ (256 * PITCH * 2)
#define STAGE_SZ (A_SZ + B_SZ)
#define GEMM_SMEM (2 * STAGE_SZ)

template <int OUT>
__global__ void __launch_bounds__(256, 2) gemm_f16x2_kernel(
    const __half* __restrict__ Ah, const __half* __restrict__ Bh,
    const float* __restrict__ bias, float* __restrict__ C,
    __half* __restrict__ Cs, int M) {
    extern __shared__ char smem[];
    uint32_t sbase = smem_u32(smem);

    int tid = threadIdx.x, lane = tid & 31, wid = tid >> 5;
    int m0 = blockIdx.x * 64;
    int wm = (wid >> 2) * 32;   // 2 warp rows cover BM=64
    int wn = (wid & 3) * 64;    // 4 warp cols cover BN=256

    int arow = tid >> 2, aq = tid & 3;   // A: 64 rows, 4 thr/row, 32B each
    int gmA = m0 + arow; if (gmA >= M) gmA = M - 1;

    float acc[2][8][4];
#pragma unroll
    for (int i = 0; i < 2; i++)
#pragma unroll
        for (int j = 0; j < 8; j++)
#pragma unroll
            for (int q = 0; q < 4; q++) acc[i][j][q] = 0.f;

    auto issue = [&](int it, int stg) {
        int kc = it >> 1, p = it & 1;
        uint32_t sA = sbase + stg * STAGE_SZ;
        uint32_t sB = sA + A_SZ;
        const __half* asrc = Ah + (size_t)gmA * 512 + p * 256 + kc * 64 + aq * 16;
        uint32_t adst = sA + (uint32_t)(arow * PITCH + aq * 16) * 2;
        CP_ASYNC16(adst, asrc);
        CP_ASYNC16(adst + 16, asrc + 8);
        const __half* bsrc = Bh + (size_t)tid * NF + kc * 64;   // B row = tid
        uint32_t bdst = sB + (uint32_t)(tid * PITCH) * 2;
#pragma unroll
        for (int j = 0; j < 8; j++) CP_ASYNC16(bdst + j * 16, bsrc + j * 8);
        CP_COMMIT();
    };

    auto compute = [&](int stg) {
        uint32_t sA = sbase + stg * STAGE_SZ;
        uint32_t sB = sA + A_SZ;
#pragma unroll
        for (int ks = 0; ks < 4; ks++) {
            uint32_t af[2][4];
#pragma unroll
            for (int mt = 0; mt < 2; mt++) {
                uint32_t addr = sA +
                    (uint32_t)((wm + mt * 16 + (lane & 15)) * PITCH + ks * 16 +
                               ((lane >> 4) << 3)) * 2;
                LDSM_X4(af[mt][0], af[mt][1], af[mt][2], af[mt][3], addr);
            }
            uint32_t bf[4][4];
#pragma unroll
            for (int p = 0; p < 4; p++) {
                uint32_t addr = sB +
                    (uint32_t)((wn + p * 16 + ((lane >> 4) << 3) + (lane & 7)) * PITCH +
                               ks * 16 + ((lane >> 3) & 1) * 8) * 2;
                LDSM_X4(bf[p][0], bf[p][1], bf[p][2], bf[p][3], addr);
            }
#pragma unroll
            for (int mt = 0; mt < 2; mt++)
#pragma unroll
                for (int nt = 0; nt < 8; nt++)
                    mma_f16(acc[mt][nt], af[mt], &bf[nt >> 1][(nt & 1) * 2]);
        }
    };

    issue(0, 0);
    for (int it = 0; it < 8; it++) {
        CP_WAIT0();              // drain group `it`
        __syncthreads();         // all warps done with the other stage
        if (it < 7) issue(it + 1, (it + 1) & 1);   // overlaps compute below
        compute(it & 1);
    }

    // epilogue: bias + relu
#pragma unroll
    for (int mt = 0; mt < 2; mt++) {
        int rr[2];
        rr[0] = m0 + wm + mt * 16 + (lane >> 2);
        rr[1] = rr[0] + 8;
#pragma unroll
        for (int nt = 0; nt < 8; nt++) {
            int n = wn + nt * 8 + (lane & 3) * 2;
            float b0 = __ldg(bias + n), b1 = __ldg(bias + n + 1);
#pragma unroll
            for (int h = 0; h < 2; h++) {
                int r = rr[h];
                if (r >= M) continue;
                float v0 = fmaxf(acc[mt][nt][h * 2 + 0] + b0, 0.f);
                float v1 = fmaxf(acc[mt][nt][h * 2 + 1] + b1, 0.f);
                if (OUT == 1) {
                    __half h0 = __float2half_rn(v0), h1 = __float2half_rn(v1);
                    __half l0 = __float2half_rn(v0 - __half2float(h0));
                    __half l1 = __float2half_rn(v1 - __half2float(h1));
                    __half ph[2] = {h0, h1}, pl[2] = {l0, l1};
                    *(uint32_t*)(Cs + (size_t)r * 512 + n) = *(uint32_t*)ph;
                    *(uint32_t*)(Cs + (size_t)r * 512 + 256 + n) = *(uint32_t*)pl;
                } else if (OUT == 2) {
                    __half ph[2] = {__float2half_rn(v0), __float2half_rn(v1)};
                    *(uint32_t*)(Cs + (size_t)r * NF + n) = *(uint32_t*)ph;
                } else {
                    float2 o; o.x = v0; o.y = v1;
                    *(float2*)(C + (size_t)r * NF + n) = o;
                }
            }
        }
    }
}

// ---------------- fused final GEMM (N=40) + log_softmax ----------------
__global__ void __launch_bounds__(256) gemm40_lsm_kernel(
    const float* __restrict__ A, const float* __restrict__ B,
    const float* __restrict__ bias, float* __restrict__ out, int M) {
    __shared__ float As[16][132];
    __shared__ float Bs[16][64];
    __shared__ float ls[128][44];
    int tid = threadIdx.x;
    int tn = tid % 16, tm = tid / 16;
    int m0 = blockIdx.x * 128;
    float acc[8][4];
#pragma unroll
    for (int i = 0; i < 8; i++)
#pragma unroll
        for (int j = 0; j < 4; j++) acc[i][j] = 0.f;

    for (int k0 = 0; k0 < NF; k0 += 16) {
        for (int i = tid; i < 128 * 16; i += 256) {
            int r = i >> 4, c = i & 15;
            int gm = m0 + r;
            As[c][r] = (gm < M) ? A[(size_t)gm * NF + k0 + c] : 0.f;
        }
        for (int i = tid; i < 16 * 64; i += 256) {
            int r = i >> 6, c = i & 63;
            Bs[r][c] = (c < 40) ? B[(size_t)(k0 + r) * 40 + c] : 0.f;
        }
        __syncthreads();
#pragma unroll
        for (int k = 0; k < 16; k++) {
            float av[8], bv[4];
#pragma unroll
            for (int i = 0; i < 8; i++) av[i] = As[k][tm * 8 + i];
#pragma unroll
            for (int j = 0; j < 4; j++) bv[j] = Bs[k][tn * 4 + j];
#pragma unroll
            for (int i = 0; i < 8; i++)
#pragma unroll
                for (int j = 0; j < 4; j++) acc[i][j] += av[i] * bv[j];
        }
        __syncthreads();
    }
#pragma unroll
    for (int i = 0; i < 8; i++)
#pragma unroll
        for (int j = 0; j < 4; j++) {
            int c = tn * 4 + j;
            if (c < 40) ls[tm * 8 + i][c] = acc[i][j] + bias[c];
        }
    __syncthreads();
    int wid = tid >> 5, lane = tid & 31;
    for (int i = 0; i < 16; i++) {
        int r = wid * 16 + i;
        int gr = m0 + r;
        if (gr >= M) continue;
        float v0 = ls[r][lane];
        float v1 = (lane < 8) ? ls[r][32 + lane] : -INFINITY;
        float m = fmaxf(v0, v1);
#pragma unroll
        for (int off = 16; off; off >>= 1) m = fmaxf(m, __shfl_xor_sync(0xffffffffu, m, off));
        float s = __expf(v0 - m) + ((lane < 8) ? __expf(v1 - m) : 0.f);
#pragma unroll
        for (int off = 16; off; off >>= 1) s += __shfl_xor_sync(0xffffffffu, s, off);
        float lse = m + __logf(s);
        out[(size_t)gr * 40 + lane] = v0 - lse;
        if (lane < 8) out[(size_t)gr * 40 + 32 + lane] = v1 - lse;
    }
}

// ---------------- launch ----------------
extern "C" void kernel_launch(void* const* d_in, const int* in_sizes, int n_in,
                              void* d_out, int out_size) {
    const float* x    = (const float*)d_in[0];
    const int*   erow = (const int*)d_in[1];
    const int*   ecol = (const int*)d_in[2];
    const float* ew   = (const float*)d_in[3];
    const float* W1 = (const float*)d_in[4];
    const float* b1 = (const float*)d_in[5];
    const float* W2 = (const float*)d_in[6];
    const float* b2 = (const float*)d_in[7];
    const float* W3 = (const float*)d_in[8];
    const float* b3 = (const float*)d_in[9];
    const float* W4 = (const float*)d_in[10];
    const float* b4 = (const float*)d_in[11];
    float* out = (float*)d_out;

    int E = in_sizes[1];
    int n = in_sizes[0] / NF;

    float *bufA, *bufB;
    __half *wh, *asp, *xh;
    int* rowptr;
    cudaGetSymbolAddress((void**)&bufA, g_bufA);
    cudaGetSymbolAddress((void**)&bufB, g_bufB);
    cudaGetSymbolAddress((void**)&rowptr, g_rowptr);
    cudaGetSymbolAddress((void**)&wh, g_Wh);
    cudaGetSymbolAddress((void**)&asp, g_Asp);
    cudaGetSymbolAddress((void**)&xh, g_xh);

    cudaFuncSetAttribute(gemm_f16x2_kernel<0>,
                         cudaFuncAttributeMaxDynamicSharedMemorySize, GEMM_SMEM);
    cudaFuncSetAttribute(gemm_f16x2_kernel<1>,
                         cudaFuncAttributeMaxDynamicSharedMemorySize, GEMM_SMEM);
    cudaFuncSetAttribute(gemm_f16x2_kernel<2>,
                         cudaFuncAttributeMaxDynamicSharedMemorySize, GEMM_SMEM);

    int total4 = n * 64;
    int chN = (total4 > E) ? total4 : E;

    // CSR build + x conv
    cudaMemsetAsync(rowptr, 0, (size_t)(n + 1) * sizeof(int));
    conv_hist_kernel<<<(chN + 255) / 256, 256>>>(x, xh, erow, E, total4);   // 1
    scan_kernel<<<1, 1024>>>(n);                                            // 2
    scatter_kernel<<<(E / 2 + 255) / 256, 256>>>(erow, ecol, ew, E);        // 3

    int spmm_blocks = (n * 64 + 255) / 256;
    int gemm_grid = (n + 63) / 64;

    // h0 = x + spmm(x)           -> Asp (fp16 split)   [4th kernel: profiled]
    spmm_f16_kernel<<<spmm_blocks, 256>>>(xh, asp, n);                      // 4

    // weight prep
    prep_w_f16<<<256, 256>>>(W1, wh + 0 * (size_t)NF * NF);
    prep_w_f16<<<256, 256>>>(W2, wh + 1 * (size_t)NF * NF);
    prep_w_f16<<<256, 256>>>(W3, wh + 2 * (size_t)NF * NF);

    // h1 = relu(h0 @ W1 + b1)    -> bufB as fp16 split [M,512]
    gemm_f16x2_kernel<1><<<gemm_grid, 256, GEMM_SMEM>>>(
        asp, wh + 0 * (size_t)NF * NF, b1, nullptr, (__half*)bufB, n);
    // h2 = relu(h1 @ W2 + b2)    -> xh (fp16 [M,256])
    gemm_f16x2_kernel<2><<<gemm_grid, 256, GEMM_SMEM>>>(
        (const __half*)bufB, wh + 1 * (size_t)NF * NF, b2, nullptr, xh, n);
    // h3 = h2 + spmm(h2)         -> Asp (fp16 split)
    spmm_f16_kernel<<<spmm_blocks, 256>>>(xh, asp, n);
    // h4 = relu(h3 @ W3 + b3)    -> bufA fp32
    gemm_f16x2_kernel<0><<<gemm_grid, 256, GEMM_SMEM>>>(
        asp, wh + 2 * (size_t)NF * NF, b3, bufA, nullptr, n);
    // logits + log_softmax       -> d_out
    gemm40_lsm_kernel<<<(n + 127) / 128, 256>>>(bufA, W4, b4, out, n);
}

// round 9
// speedup vs baseline: 1.4112x; 1.4112x over previous
#include <cuda_runtime.h>
#include <cuda_fp16.h>
#include <math.h>
#include <stdint.h>

#define NNODES 100000
#define NEDGES 3200000
#define NF 256

// ---------------- scratch (device globals; no allocs allowed) ----------------
__device__ float g_bufA[(size_t)NNODES * NF];           // fp32 [M,256] (h4)
__device__ __half g_h0[(size_t)NNODES * NF];            // fp16 ping
__device__ __half g_h1[(size_t)NNODES * NF];            // fp16 pong
__device__ int   g_rowptr[NNODES + 1];
__device__ int   g_cursor[NNODES];
__device__ uint2 g_cw[NEDGES];                          // packed {col, weight-bits}
__device__ __half g_Wh[3][NF * NF];                     // fp16 weights, [N][K] K-major

// ---------------- helpers ----------------
__device__ __forceinline__ uint32_t smem_u32(const void* p) {
    uint32_t a;
    asm("{ .reg .u64 t; cvta.to.shared.u64 t, %1; cvt.u32.u64 %0, t; }" : "=r"(a) : "l"(p));
    return a;
}

#define LDSM_X4(r0, r1, r2, r3, addr) \
    asm volatile("ldmatrix.sync.aligned.m8n8.x4.shared.b16 {%0,%1,%2,%3}, [%4];" \
                 : "=r"(r0), "=r"(r1), "=r"(r2), "=r"(r3) : "r"(addr))

__device__ __forceinline__ void mma_f16(float* d, const uint32_t* a, const uint32_t* b) {
    asm volatile(
        "mma.sync.aligned.m16n8k16.row.col.f32.f16.f16.f32 "
        "{%0,%1,%2,%3}, {%4,%5,%6,%7}, {%8,%9}, {%0,%1,%2,%3};"
        : "+f"(d[0]), "+f"(d[1]), "+f"(d[2]), "+f"(d[3])
        : "r"(a[0]), "r"(a[1]), "r"(a[2]), "r"(a[3]), "r"(b[0]), "r"(b[1]));
}

#define CP_ASYNC16(dst, src) \
    asm volatile("cp.async.cg.shared.global [%0], [%1], 16;" :: "r"(dst), "l"(src))
#define CP_COMMIT() asm volatile("cp.async.commit_group;")
#define CP_WAIT1() asm volatile("cp.async.wait_group 1;")
#define CP_WAIT0() asm volatile("cp.async.wait_group 0;")

// ---------------- merged: x -> fp16 copy + degree histogram ----------------
__global__ void conv_hist_kernel(const float* __restrict__ x, __half* __restrict__ xh,
                                 const int* __restrict__ erow, int E, int total4) {
    int i = blockIdx.x * blockDim.x + threadIdx.x;
    if (i < total4) {
        float4 v = ((const float4*)x)[i];
        __half h[4] = {__float2half_rn(v.x), __float2half_rn(v.y),
                       __float2half_rn(v.z), __float2half_rn(v.w)};
        *(uint2*)(xh + (size_t)i * 4) = *(uint2*)h;
    }
    if (i < E) atomicAdd(&g_rowptr[erow[i]], 1);
}

__global__ void scan_kernel(int n) {
    __shared__ int part[1024];
    int t = threadIdx.x;
    int CH = (n + 1023) / 1024;
    int beg = t * CH;
    int end = min(beg + CH, n);
    int s = 0;
    for (int i = beg; i < end; i++) s += g_rowptr[i];
    part[t] = s;
    __syncthreads();
    for (int off = 1; off < 1024; off <<= 1) {
        int v = (t >= off) ? part[t - off] : 0;
        __syncthreads();
        part[t] += v;
        __syncthreads();
    }
    int base = (t == 0) ? 0 : part[t - 1];
    int run = base;
    for (int i = beg; i < end; i++) {
        int c = g_rowptr[i];
        g_rowptr[i] = run;
        g_cursor[i] = run;
        run += c;
    }
    if (t == 1023) g_rowptr[n] = part[1023];
}

__global__ void scatter_kernel(const int* __restrict__ erow,
                               const int* __restrict__ ecol,
                               const float* __restrict__ ew, int E) {
    int i = (blockIdx.x * blockDim.x + threadIdx.x) * 2;
#pragma unroll
    for (int j = 0; j < 2; j++) {
        if (i + j < E) {
            int r = erow[i + j];
            int pos = atomicAdd(&g_cursor[r], 1);
            uint2 cw;
            cw.x = (uint32_t)ecol[i + j];
            cw.y = __float_as_uint(ew[i + j]);
            g_cw[pos] = cw;
        }
    }
}

// ---------------- SPMM (fp16 gather, packed edges) + residual -> fp16 ----------------
__global__ void spmm_f16_kernel(const __half* __restrict__ src,
                                __half* __restrict__ dst, int n) {
    int gw = (blockIdx.x * blockDim.x + threadIdx.x) >> 5;
    int row = gw >> 1;
    if (row >= n) return;
    int half_ = gw & 1;
    int lane = threadIdx.x & 31;
    int f4 = half_ * 32 + lane;
    const uint2* s2 = (const uint2*)src;
    uint2 rv = s2[(size_t)row * 64 + f4];
    float2 p0 = __half22float2(*(__half2*)&rv.x);
    float2 p1 = __half22float2(*(__half2*)&rv.y);
    float ax = p0.x, ay = p0.y, az = p1.x, aw = p1.y;
    int beg = g_rowptr[row], end = g_rowptr[row + 1];
    int e = beg;
    for (; e + 4 <= end; e += 4) {
        uint2 cw0 = __ldg(&g_cw[e]),     cw1 = __ldg(&g_cw[e + 1]);
        uint2 cw2 = __ldg(&g_cw[e + 2]), cw3 = __ldg(&g_cw[e + 3]);
        float w0 = __uint_as_float(cw0.y), w1 = __uint_as_float(cw1.y);
        float w2 = __uint_as_float(cw2.y), w3 = __uint_as_float(cw3.y);
        uint2 v0 = s2[(size_t)cw0.x * 64 + f4];
        uint2 v1 = s2[(size_t)cw1.x * 64 + f4];
        uint2 v2 = s2[(size_t)cw2.x * 64 + f4];
        uint2 v3 = s2[(size_t)cw3.x * 64 + f4];
        float2 a0 = __half22float2(*(__half2*)&v0.x), b0 = __half22float2(*(__half2*)&v0.y);
        float2 a1 = __half22float2(*(__half2*)&v1.x), b1 = __half22float2(*(__half2*)&v1.y);
        float2 a2 = __half22float2(*(__half2*)&v2.x), b2 = __half22float2(*(__half2*)&v2.y);
        float2 a3 = __half22float2(*(__half2*)&v3.x), b3 = __half22float2(*(__half2*)&v3.y);
        ax += w0 * a0.x + w1 * a1.x + w2 * a2.x + w3 * a3.x;
        ay += w0 * a0.y + w1 * a1.y + w2 * a2.y + w3 * a3.y;
        az += w0 * b0.x + w1 * b1.x + w2 * b2.x + w3 * b3.x;
        aw += w0 * b0.y + w1 * b1.y + w2 * b2.y + w3 * b3.y;
    }
    for (; e < end; e++) {
        uint2 cw = __ldg(&g_cw[e]);
        float w = __uint_as_float(cw.y);
        uint2 v = s2[(size_t)cw.x * 64 + f4];
        float2 a = __half22float2(*(__half2*)&v.x), b = __half22float2(*(__half2*)&v.y);
        ax += w * a.x; ay += w * a.y; az += w * b.x; aw += w * b.y;
    }
    __half o[4] = {__float2half_rn(ax), __float2half_rn(ay),
                   __float2half_rn(az), __float2half_rn(aw)};
    *(uint2*)(dst + (size_t)row * 256 + f4 * 4) = *(uint2*)o;
}

// ---------------- weight prep: W[K][N] fp32 -> Wh[N][K] fp16 ----------------
__global__ void prep_w_f16(const float* __restrict__ W, __half* __restrict__ Bh) {
    int n = blockIdx.x;
    int k = threadIdx.x;
    Bh[(size_t)n * NF + k] = __float2half_rn(W[(size_t)k * NF + n]);
}

// ---------------- fp16 GEMM: BM=128, BN=128, BK=64, K=256, 3-stage, occ=2 ----------------
// A: fp16 [M,256]; B: fp16 [256,256] K-major. grid=(ceil(M/128), 2).
// OUT: 0 -> fp32 [M,256]; 2 -> fp16 [M,256]
#define PITCH 72
#define A_SZ (128 * PITCH * 2)
#define B_SZ (128 * PITCH * 2)
#define STAGE_SZ (A_SZ + B_SZ)
#define GEMM_SMEM (3 * STAGE_SZ)

template <int OUT>
__global__ void __launch_bounds__(256, 2) gemm_f16_kernel(
    const __half* __restrict__ Ah, const __half* __restrict__ Bh,
    const float* __restrict__ bias, float* __restrict__ C,
    __half* __restrict__ Cs, int M) {
    extern __shared__ char smem[];
    uint32_t sbase = smem_u32(smem);

    int tid = threadIdx.x, lane = tid & 31, wid = tid >> 5;
    int m0 = blockIdx.x * 128;
    int n0 = blockIdx.y * 128;
    int wm = (wid >> 1) * 32;
    int wn = (wid & 1) * 64;

    int arow = tid >> 1, aq = tid & 1;   // 2 thr/row, 32 halves (64B) each
    int gmA = m0 + arow; if (gmA >= M) gmA = M - 1;

    float acc[2][8][4];
#pragma unroll
    for (int i = 0; i < 2; i++)
#pragma unroll
        for (int j = 0; j < 8; j++)
#pragma unroll
            for (int q = 0; q < 4; q++) acc[i][j][q] = 0.f;

    auto issue = [&](int it, int stg) {
        uint32_t sA = sbase + stg * STAGE_SZ;
        uint32_t sB = sA + A_SZ;
        const __half* asrc = Ah + (size_t)gmA * NF + it * 64 + aq * 32;
        uint32_t adst = sA + (uint32_t)(arow * PITCH + aq * 32) * 2;
#pragma unroll
        for (int j = 0; j < 4; j++) CP_ASYNC16(adst + j * 16, asrc + j * 8);
        const __half* bsrc = Bh + (size_t)(n0 + arow) * NF + it * 64 + aq * 32;
        uint32_t bdst = sB + (uint32_t)(arow * PITCH + aq * 32) * 2;
#pragma unroll
        for (int j = 0; j < 4; j++) CP_ASYNC16(bdst + j * 16, bsrc + j * 8);
        CP_COMMIT();
    };

    auto compute = [&](int stg) {
        uint32_t sA = sbase + stg * STAGE_SZ;
        uint32_t sB = sA + A_SZ;
#pragma unroll
        for (int ks = 0; ks < 4; ks++) {
            uint32_t af[2][4];
#pragma unroll
            for (int mt = 0; mt < 2; mt++) {
                uint32_t addr = sA +
                    (uint32_t)((wm + mt * 16 + (lane & 15)) * PITCH + ks * 16 +
                               ((lane >> 4) << 3)) * 2;
                LDSM_X4(af[mt][0], af[mt][1], af[mt][2], af[mt][3], addr);
            }
            uint32_t bf[4][4];
#pragma unroll
            for (int p = 0; p < 4; p++) {
                uint32_t addr = sB +
                    (uint32_t)((wn + p * 16 + ((lane >> 4) << 3) + (lane & 7)) * PITCH +
                               ks * 16 + ((lane >> 3) & 1) * 8) * 2;
                LDSM_X4(bf[p][0], bf[p][1], bf[p][2], bf[p][3], addr);
            }
#pragma unroll
            for (int mt = 0; mt < 2; mt++)
#pragma unroll
                for (int nt = 0; nt < 8; nt++)
                    mma_f16(acc[mt][nt], af[mt], &bf[nt >> 1][(nt & 1) * 2]);
        }
    };

    issue(0, 0);
    issue(1, 1);
    for (int it = 0; it < 4; it++) {
        if (it < 3) CP_WAIT1(); else CP_WAIT0();
        __syncthreads();
        compute(it % 3);
        if (it + 2 < 4) issue(it + 2, (it + 2) % 3);
    }

    // epilogue: bias + relu
#pragma unroll
    for (int mt = 0; mt < 2; mt++) {
        int rr[2];
        rr[0] = m0 + wm + mt * 16 + (lane >> 2);
        rr[1] = rr[0] + 8;
#pragma unroll
        for (int nt = 0; nt < 8; nt++) {
            int n = n0 + wn + nt * 8 + (lane & 3) * 2;
            float b0 = __ldg(bias + n), b1 = __ldg(bias + n + 1);
#pragma unroll
            for (int h = 0; h < 2; h++) {
                int r = rr[h];
                if (r >= M) continue;
                float v0 = fmaxf(acc[mt][nt][h * 2 + 0] + b0, 0.f);
                float v1 = fmaxf(acc[mt][nt][h * 2 + 1] + b1, 0.f);
                if (OUT == 2) {
                    __half ph[2] = {__float2half_rn(v0), __float2half_rn(v1)};
                    *(uint32_t*)(Cs + (size_t)r * NF + n) = *(uint32_t*)ph;
                } else {
                    float2 o; o.x = v0; o.y = v1;
                    *(float2*)(C + (size_t)r * NF + n) = o;
                }
            }
        }
    }
}

// ---------------- fused final GEMM (N=40) + log_softmax ----------------
__global__ void __launch_bounds__(256) gemm40_lsm_kernel(
    const float* __restrict__ A, const float* __restrict__ B,
    const float* __restrict__ bias, float* __restrict__ out, int M) {
    __shared__ float As[16][132];
    __shared__ float Bs[16][64];
    __shared__ float ls[128][44];
    int tid = threadIdx.x;
    int tn = tid % 16, tm = tid / 16;
    int m0 = blockIdx.x * 128;
    float acc[8][4];
#pragma unroll
    for (int i = 0; i < 8; i++)
#pragma unroll
        for (int j = 0; j < 4; j++) acc[i][j] = 0.f;

    for (int k0 = 0; k0 < NF; k0 += 16) {
        for (int i = tid; i < 128 * 16; i += 256) {
            int r = i >> 4, c = i & 15;
            int gm = m0 + r;
            As[c][r] = (gm < M) ? A[(size_t)gm * NF + k0 + c] : 0.f;
        }
        for (int i = tid; i < 16 * 64; i += 256) {
            int r = i >> 6, c = i & 63;
            Bs[r][c] = (c < 40) ? B[(size_t)(k0 + r) * 40 + c] : 0.f;
        }
        __syncthreads();
#pragma unroll
        for (int k = 0; k < 16; k++) {
            float av[8], bv[4];
#pragma unroll
            for (int i = 0; i < 8; i++) av[i] = As[k][tm * 8 + i];
#pragma unroll
            for (int j = 0; j < 4; j++) bv[j] = Bs[k][tn * 4 + j];
#pragma unroll
            for (int i = 0; i < 8; i++)
#pragma unroll
                for (int j = 0; j < 4; j++) acc[i][j] += av[i] * bv[j];
        }
        __syncthreads();
    }
#pragma unroll
    for (int i = 0; i < 8; i++)
#pragma unroll
        for (int j = 0; j < 4; j++) {
            int c = tn * 4 + j;
            if (c < 40) ls[tm * 8 + i][c] = acc[i][j] + bias[c];
        }
    __syncthreads();
    int wid = tid >> 5, lane = tid & 31;
    for (int i = 0; i < 16; i++) {
        int r = wid * 16 + i;
        int gr = m0 + r;
        if (gr >= M) continue;
        float v0 = ls[r][lane];
        float v1 = (lane < 8) ? ls[r][32 + lane] : -INFINITY;
        float m = fmaxf(v0, v1);
#pragma unroll
        for (int off = 16; off; off >>= 1) m = fmaxf(m, __shfl_xor_sync(0xffffffffu, m, off));
        float s = __expf(v0 - m) + ((lane < 8) ? __expf(v1 - m) : 0.f);
#pragma unroll
        for (int off = 16; off; off >>= 1) s += __shfl_xor_sync(0xffffffffu, s, off);
        float lse = m + __logf(s);
        out[(size_t)gr * 40 + lane] = v0 - lse;
        if (lane < 8) out[(size_t)gr * 40 + 32 + lane] = v1 - lse;
    }
}

// ---------------- launch ----------------
extern "C" void kernel_launch(void* const* d_in, const int* in_sizes, int n_in,
                              void* d_out, int out_size) {
    const float* x    = (const float*)d_in[0];
    const int*   erow = (const int*)d_in[1];
    const int*   ecol = (const int*)d_in[2];
    const float* ew   = (const float*)d_in[3];
    const float* W1 = (const float*)d_in[4];
    const float* b1 = (const float*)d_in[5];
    const float* W2 = (const float*)d_in[6];
    const float* b2 = (const float*)d_in[7];
    const float* W3 = (const float*)d_in[8];
    const float* b3 = (const float*)d_in[9];
    const float* W4 = (const float*)d_in[10];
    const float* b4 = (const float*)d_in[11];
    float* out = (float*)d_out;

    int E = in_sizes[1];
    int n = in_sizes[0] / NF;

    float* bufA;
    __half *wh, *h0, *h1;
    int* rowptr;
    cudaGetSymbolAddress((void**)&bufA, g_bufA);
    cudaGetSymbolAddress((void**)&rowptr, g_rowptr);
    cudaGetSymbolAddress((void**)&wh, g_Wh);
    cudaGetSymbolAddress((void**)&h0, g_h0);
    cudaGetSymbolAddress((void**)&h1, g_h1);

    cudaFuncSetAttribute(gemm_f16_kernel<0>,
                         cudaFuncAttributeMaxDynamicSharedMemorySize, GEMM_SMEM);
    cudaFuncSetAttribute(gemm_f16_kernel<2>,
                         cudaFuncAttributeMaxDynamicSharedMemorySize, GEMM_SMEM);

    int total4 = n * 64;
    int chN = (total4 > E) ? total4 : E;

    // CSR build + x conv
    cudaMemsetAsync(rowptr, 0, (size_t)(n + 1) * sizeof(int));
    conv_hist_kernel<<<(chN + 255) / 256, 256>>>(x, h0, erow, E, total4);   // 1
    scan_kernel<<<1, 1024>>>(n);                                            // 2
    scatter_kernel<<<(E / 2 + 255) / 256, 256>>>(erow, ecol, ew, E);        // 3

    int spmm_blocks = (n * 64 + 255) / 256;
    dim3 gemm_grid((n + 127) / 128, 2);

    // h0g = x + spmm(x): h0 -> h1                      [4th kernel: profiled]
    spmm_f16_kernel<<<spmm_blocks, 256>>>(h0, h1, n);

    // weight prep
    prep_w_f16<<<256, 256>>>(W1, wh + 0 * (size_t)NF * NF);
    prep_w_f16<<<256, 256>>>(W2, wh + 1 * (size_t)NF * NF);
    prep_w_f16<<<256, 256>>>(W3, wh + 2 * (size_t)NF * NF);

    // h1g = relu(h0g @ W1 + b1): h1 -> h0
    gemm_f16_kernel<2><<<gemm_grid, 256, GEMM_SMEM>>>(
        h1, wh + 0 * (size_t)NF * NF, b1, nullptr, h0, n);
    // h2g = relu(h1g @ W2 + b2): h0 -> h1
    gemm_f16_kernel<2><<<gemm_grid, 256, GEMM_SMEM>>>(
        h0, wh + 1 * (size_t)NF * NF, b2, nullptr, h1, n);
    // h3g = h2g + spmm(h2g): h1 -> h0
    spmm_f16_kernel<<<spmm_blocks, 256>>>(h1, h0, n);
    // h4g = relu(h3g @ W3 + b3): h0 -> bufA (fp32)
    gemm_f16_kernel<0><<<gemm_grid, 256, GEMM_SMEM>>>(
        h0, wh + 2 * (size_t)NF * NF, b3, bufA, nullptr, n);
    // logits + log_softmax       -> d_out
    gemm40_lsm_kernel<<<(n + 127) / 128, 256>>>(bufA, W4, b4, out, n);
}

// round 10
// speedup vs baseline: 1.5019x; 1.0643x over previous
#include <cuda_runtime.h>
#include <cuda_fp16.h>
#include <math.h>
#include <stdint.h>

#define NNODES 100000
#define NEDGES 3200000
#define NF 256

// ---------------- scratch (device globals; no allocs allowed) ----------------
__device__ __half g_h0[(size_t)NNODES * NF];            // fp16 ping
__device__ __half g_h1[(size_t)NNODES * NF];            // fp16 pong
__device__ int   g_rowptr[NNODES + 1];
__device__ int   g_cursor[NNODES];
__device__ uint2 g_cw[NEDGES];                          // packed {col, weight-bits}
__device__ __half g_Wh[3][NF * NF];                     // fp16 weights, [N][K] K-major

// ---------------- helpers ----------------
__device__ __forceinline__ uint32_t smem_u32(const void* p) {
    uint32_t a;
    asm("{ .reg .u64 t; cvta.to.shared.u64 t, %1; cvt.u32.u64 %0, t; }" : "=r"(a) : "l"(p));
    return a;
}

#define LDSM_X4(r0, r1, r2, r3, addr) \
    asm volatile("ldmatrix.sync.aligned.m8n8.x4.shared.b16 {%0,%1,%2,%3}, [%4];" \
                 : "=r"(r0), "=r"(r1), "=r"(r2), "=r"(r3) : "r"(addr))

__device__ __forceinline__ void mma_f16(float* d, const uint32_t* a, const uint32_t* b) {
    asm volatile(
        "mma.sync.aligned.m16n8k16.row.col.f32.f16.f16.f32 "
        "{%0,%1,%2,%3}, {%4,%5,%6,%7}, {%8,%9}, {%0,%1,%2,%3};"
        : "+f"(d[0]), "+f"(d[1]), "+f"(d[2]), "+f"(d[3])
        : "r"(a[0]), "r"(a[1]), "r"(a[2]), "r"(a[3]), "r"(b[0]), "r"(b[1]));
}

#define CP_ASYNC16(dst, src) \
    asm volatile("cp.async.cg.shared.global [%0], [%1], 16;" :: "r"(dst), "l"(src))
#define CP_COMMIT() asm volatile("cp.async.commit_group;")
#define CP_WAIT1() asm volatile("cp.async.wait_group 1;")
#define CP_WAIT0() asm volatile("cp.async.wait_group 0;")

// ---------------- merged: x -> fp16 copy + degree histogram ----------------
__global__ void conv_hist_kernel(const float* __restrict__ x, __half* __restrict__ xh,
                                 const int* __restrict__ erow, int E, int total4) {
    int i = blockIdx.x * blockDim.x + threadIdx.x;
    if (i < total4) {
        float4 v = ((const float4*)x)[i];
        __half h[4] = {__float2half_rn(v.x), __float2half_rn(v.y),
                       __float2half_rn(v.z), __float2half_rn(v.w)};
        *(uint2*)(xh + (size_t)i * 4) = *(uint2*)h;
    }
    if (i < E) atomicAdd(&g_rowptr[erow[i]], 1);
}

__global__ void scan_kernel(int n) {
    __shared__ int part[1024];
    int t = threadIdx.x;
    int CH = (n + 1023) / 1024;
    int beg = t * CH;
    int end = min(beg + CH, n);
    int s = 0;
    for (int i = beg; i < end; i++) s += g_rowptr[i];
    part[t] = s;
    __syncthreads();
    for (int off = 1; off < 1024; off <<= 1) {
        int v = (t >= off) ? part[t - off] : 0;
        __syncthreads();
        part[t] += v;
        __syncthreads();
    }
    int base = (t == 0) ? 0 : part[t - 1];
    int run = base;
    for (int i = beg; i < end; i++) {
        int c = g_rowptr[i];
        g_rowptr[i] = run;
        g_cursor[i] = run;
        run += c;
    }
    if (t == 1023) g_rowptr[n] = part[1023];
}

__global__ void scatter_kernel(const int* __restrict__ erow,
                               const int* __restrict__ ecol,
                               const float* __restrict__ ew, int E) {
    int i = (blockIdx.x * blockDim.x + threadIdx.x) * 2;
#pragma unroll
    for (int j = 0; j < 2; j++) {
        if (i + j < E) {
            int r = erow[i + j];
            int pos = atomicAdd(&g_cursor[r], 1);
            uint2 cw;
            cw.x = (uint32_t)ecol[i + j];
            cw.y = __float_as_uint(ew[i + j]);
            g_cw[pos] = cw;
        }
    }
}

// ---------------- SPMM (fp16 gather, packed edges) + residual -> fp16 ----------------
__global__ void spmm_f16_kernel(const __half* __restrict__ src,
                                __half* __restrict__ dst, int n) {
    int gw = (blockIdx.x * blockDim.x + threadIdx.x) >> 5;
    int row = gw >> 1;
    if (row >= n) return;
    int half_ = gw & 1;
    int lane = threadIdx.x & 31;
    int f4 = half_ * 32 + lane;
    const uint2* s2 = (const uint2*)src;
    uint2 rv = s2[(size_t)row * 64 + f4];
    float2 p0 = __half22float2(*(__half2*)&rv.x);
    float2 p1 = __half22float2(*(__half2*)&rv.y);
    float ax = p0.x, ay = p0.y, az = p1.x, aw = p1.y;
    int beg = g_rowptr[row], end = g_rowptr[row + 1];
    int e = beg;
    for (; e + 4 <= end; e += 4) {
        uint2 cw0 = __ldg(&g_cw[e]),     cw1 = __ldg(&g_cw[e + 1]);
        uint2 cw2 = __ldg(&g_cw[e + 2]), cw3 = __ldg(&g_cw[e + 3]);
        float w0 = __uint_as_float(cw0.y), w1 = __uint_as_float(cw1.y);
        float w2 = __uint_as_float(cw2.y), w3 = __uint_as_float(cw3.y);
        uint2 v0 = s2[(size_t)cw0.x * 64 + f4];
        uint2 v1 = s2[(size_t)cw1.x * 64 + f4];
        uint2 v2 = s2[(size_t)cw2.x * 64 + f4];
        uint2 v3 = s2[(size_t)cw3.x * 64 + f4];
        float2 a0 = __half22float2(*(__half2*)&v0.x), b0 = __half22float2(*(__half2*)&v0.y);
        float2 a1 = __half22float2(*(__half2*)&v1.x), b1 = __half22float2(*(__half2*)&v1.y);
        float2 a2 = __half22float2(*(__half2*)&v2.x), b2 = __half22float2(*(__half2*)&v2.y);
        float2 a3 = __half22float2(*(__half2*)&v3.x), b3 = __half22float2(*(__half2*)&v3.y);
        ax += w0 * a0.x + w1 * a1.x + w2 * a2.x + w3 * a3.x;
        ay += w0 * a0.y + w1 * a1.y + w2 * a2.y + w3 * a3.y;
        az += w0 * b0.x + w1 * b1.x + w2 * b2.x + w3 * b3.x;
        aw += w0 * b0.y + w1 * b1.y + w2 * b2.y + w3 * b3.y;
    }
    for (; e < end; e++) {
        uint2 cw = __ldg(&g_cw[e]);
        float w = __uint_as_float(cw.y);
        uint2 v = s2[(size_t)cw.x * 64 + f4];
        float2 a = __half22float2(*(__half2*)&v.x), b = __half22float2(*(__half2*)&v.y);
        ax += w * a.x; ay += w * a.y; az += w * b.x; aw += w * b.y;
    }
    __half o[4] = {__float2half_rn(ax), __float2half_rn(ay),
                   __float2half_rn(az), __float2half_rn(aw)};
    *(uint2*)(dst + (size_t)row * 256 + f4 * 4) = *(uint2*)o;
}

// ---------------- weight prep: 3 layers in one launch ----------------
__global__ void prep_w_f16(const float* __restrict__ W1, const float* __restrict__ W2,
                           const float* __restrict__ W3, __half* __restrict__ Bh) {
    int n = blockIdx.x;
    int k = threadIdx.x;
    int l = blockIdx.y;
    const float* W = (l == 0) ? W1 : (l == 1) ? W2 : W3;
    Bh[(size_t)l * NF * NF + (size_t)n * NF + k] = __float2half_rn(W[(size_t)k * NF + n]);
}

// ---------------- fused GEMM1+GEMM2: h2 = relu(relu(h0@W1+b1)@W2+b2) ----------------
// 512 threads, BM=128, BN=256 (full N), BK=64, phase1 3-stage, h1 in smem, phase2 2-buf.
#define PITCH 72
#define A_SZ1 (128 * PITCH * 2)          // 18432
#define B_SZ1 (256 * PITCH * 2)          // 36864
#define STAGE1 (A_SZ1 + B_SZ1)           // 55296
#define FUSED_SMEM (3 * STAGE1)          // 165888
#define H1_PITCH 264
#define H1_OFF 0                         // h1: 128*264*2 = 67584 bytes
#define B2_OFF0 68608                    // phase2 W2 buffers (36864 each)
#define B2_OFF1 (68608 + 36864)          // ends 142336 < 165888

__global__ void __launch_bounds__(512) fused_mlp2_kernel(
    const __half* __restrict__ Ah, const __half* __restrict__ W1h,
    const float* __restrict__ b1, const __half* __restrict__ W2h,
    const float* __restrict__ b2, __half* __restrict__ Out, int M) {
    extern __shared__ char smem[];
    uint32_t sbase = smem_u32(smem);
    uint32_t sh1 = sbase + H1_OFF;

    int tid = threadIdx.x, lane = tid & 31, wid = tid >> 5;
    int m0 = blockIdx.x * 128;
    int wm = (wid >> 2) * 32;
    int wn = (wid & 3) * 64;

    int arow = tid >> 2, aq = tid & 3;     // A loader: 128 rows, 4 thr/row, 32B each
    int gmA = m0 + arow; if (gmA >= M) gmA = M - 1;
    int brow = tid >> 1, bh = tid & 1;     // B loader: 256 rows, 2 thr/row, 64B each

    float acc[2][8][4];
#pragma unroll
    for (int i = 0; i < 2; i++)
#pragma unroll
        for (int j = 0; j < 8; j++)
#pragma unroll
            for (int q = 0; q < 4; q++) acc[i][j][q] = 0.f;

    // ---- phase 1: h0 @ W1 ----
    auto issue1 = [&](int it, int stg) {
        uint32_t sA = sbase + stg * STAGE1;
        uint32_t sB = sA + A_SZ1;
        const __half* asrc = Ah + (size_t)gmA * NF + it * 64 + aq * 16;
        uint32_t adst = sA + (uint32_t)(arow * PITCH + aq * 16) * 2;
        CP_ASYNC16(adst, asrc);
        CP_ASYNC16(adst + 16, asrc + 8);
        const __half* bsrc = W1h + (size_t)brow * NF + it * 64 + bh * 32;
        uint32_t bdst = sB + (uint32_t)(brow * PITCH + bh * 32) * 2;
#pragma unroll
        for (int j = 0; j < 4; j++) CP_ASYNC16(bdst + j * 16, bsrc + j * 8);
        CP_COMMIT();
    };

    auto compute1 = [&](int stg) {
        uint32_t sA = sbase + stg * STAGE1;
        uint32_t sB = sA + A_SZ1;
#pragma unroll
        for (int ks = 0; ks < 4; ks++) {
            uint32_t af[2][4];
#pragma unroll
            for (int mt = 0; mt < 2; mt++) {
                uint32_t addr = sA +
                    (uint32_t)((wm + mt * 16 + (lane & 15)) * PITCH + ks * 16 +
                               ((lane >> 4) << 3)) * 2;
                LDSM_X4(af[mt][0], af[mt][1], af[mt][2], af[mt][3], addr);
            }
            uint32_t bf[4][4];
#pragma unroll
            for (int p = 0; p < 4; p++) {
                uint32_t addr = sB +
                    (uint32_t)((wn + p * 16 + ((lane >> 4) << 3) + (lane & 7)) * PITCH +
                               ks * 16 + ((lane >> 3) & 1) * 8) * 2;
                LDSM_X4(bf[p][0], bf[p][1], bf[p][2], bf[p][3], addr);
            }
#pragma unroll
            for (int mt = 0; mt < 2; mt++)
#pragma unroll
                for (int nt = 0; nt < 8; nt++)
                    mma_f16(acc[mt][nt], af[mt], &bf[nt >> 1][(nt & 1) * 2]);
        }
    };

    issue1(0, 0);
    issue1(1, 1);
    for (int it = 0; it < 4; it++) {
        if (it < 3) CP_WAIT1(); else CP_WAIT0();
        __syncthreads();
        compute1(it % 3);
        if (it + 2 < 4) issue1(it + 2, (it + 2) % 3);
    }
    __syncthreads();   // all warps done reading stage buffers

    // ---- h1 = relu(acc + b1) -> smem (fp16, pitch 264), reset acc ----
#pragma unroll
    for (int mt = 0; mt < 2; mt++) {
        int r0 = wm + mt * 16 + (lane >> 2);
#pragma unroll
        for (int nt = 0; nt < 8; nt++) {
            int n = wn + nt * 8 + (lane & 3) * 2;
            float c0 = __ldg(b1 + n), c1 = __ldg(b1 + n + 1);
#pragma unroll
            for (int h = 0; h < 2; h++) {
                int r = r0 + h * 8;
                __half ph[2] = {
                    __float2half_rn(fmaxf(acc[mt][nt][h * 2 + 0] + c0, 0.f)),
                    __float2half_rn(fmaxf(acc[mt][nt][h * 2 + 1] + c1, 0.f))};
                asm volatile("st.shared.b32 [%0], %1;"
                             :: "r"(sh1 + (uint32_t)(r * H1_PITCH + n) * 2),
                                "r"(*(uint32_t*)ph));
                acc[mt][nt][h * 2 + 0] = 0.f;
                acc[mt][nt][h * 2 + 1] = 0.f;
            }
        }
    }
    __syncthreads();

    // ---- phase 2: h1(smem) @ W2 ----
    uint32_t sB2[2] = {sbase + B2_OFF0, sbase + B2_OFF1};

    auto issue2 = [&](int kc, int buf) {
        const __half* bsrc = W2h + (size_t)brow * NF + kc * 64 + bh * 32;
        uint32_t bdst = sB2[buf] + (uint32_t)(brow * PITCH + bh * 32) * 2;
#pragma unroll
        for (int j = 0; j < 4; j++) CP_ASYNC16(bdst + j * 16, bsrc + j * 8);
        CP_COMMIT();
    };

    auto compute2 = [&](int kc, int buf) {
        uint32_t sB = sB2[buf];
#pragma unroll
        for (int ks = 0; ks < 4; ks++) {
            uint32_t af[2][4];
#pragma unroll
            for (int mt = 0; mt < 2; mt++) {
                uint32_t addr = sh1 +
                    (uint32_t)((wm + mt * 16 + (lane & 15)) * H1_PITCH + kc * 64 +
                               ks * 16 + ((lane >> 4) << 3)) * 2;
                LDSM_X4(af[mt][0], af[mt][1], af[mt][2], af[mt][3], addr);
            }
            uint32_t bf[4][4];
#pragma unroll
            for (int p = 0; p < 4; p++) {
                uint32_t addr = sB +
                    (uint32_t)((wn + p * 16 + ((lane >> 4) << 3) + (lane & 7)) * PITCH +
                               ks * 16 + ((lane >> 3) & 1) * 8) * 2;
                LDSM_X4(bf[p][0], bf[p][1], bf[p][2], bf[p][3], addr);
            }
#pragma unroll
            for (int mt = 0; mt < 2; mt++)
#pragma unroll
                for (int nt = 0; nt < 8; nt++)
                    mma_f16(acc[mt][nt], af[mt], &bf[nt >> 1][(nt & 1) * 2]);
        }
    };

    issue2(0, 0);
    issue2(1, 1);
    for (int kc = 0; kc < 4; kc++) {
        if (kc < 3) CP_WAIT1(); else CP_WAIT0();
        __syncthreads();
        compute2(kc, kc & 1);
        if (kc + 2 < 4) {
            __syncthreads();          // buffer kc&1 free
            issue2(kc + 2, kc & 1);
        }
    }

    // ---- epilogue: h2 = relu(acc + b2) -> gmem fp16 ----
#pragma unroll
    for (int mt = 0; mt < 2; mt++) {
        int rr[2];
        rr[0] = m0 + wm + mt * 16 + (lane >> 2);
        rr[1] = rr[0] + 8;
#pragma unroll
        for (int nt = 0; nt < 8; nt++) {
            int n = wn + nt * 8 + (lane & 3) * 2;
            float c0 = __ldg(b2 + n), c1 = __ldg(b2 + n + 1);
#pragma unroll
            for (int h = 0; h < 2; h++) {
                int r = rr[h];
                if (r >= M) continue;
                __half ph[2] = {
                    __float2half_rn(fmaxf(acc[mt][nt][h * 2 + 0] + c0, 0.f)),
                    __float2half_rn(fmaxf(acc[mt][nt][h * 2 + 1] + c1, 0.f))};
                *(uint32_t*)(Out + (size_t)r * NF + n) = *(uint32_t*)ph;
            }
        }
    }
}

// ---------------- fp16 GEMM (layer 3): BM=128, BN=128, 3-stage, occ=2, fp16 out ----------------
#define A_SZ (128 * PITCH * 2)
#define B_SZ (128 * PITCH * 2)
#define STAGE_SZ (A_SZ + B_SZ)
#define GEMM_SMEM (3 * STAGE_SZ)

__global__ void __launch_bounds__(256, 2) gemm_f16_kernel(
    const __half* __restrict__ Ah, const __half* __restrict__ Bh,
    const float* __restrict__ bias, __half* __restrict__ Cs, int M) {
    extern __shared__ char smem[];
    uint32_t sbase = smem_u32(smem);

    int tid = threadIdx.x, lane = tid & 31, wid = tid >> 5;
    int m0 = blockIdx.x * 128;
    int n0 = blockIdx.y * 128;
    int wm = (wid >> 1) * 32;
    int wn = (wid & 1) * 64;

    int arow = tid >> 1, aq = tid & 1;
    int gmA = m0 + arow; if (gmA >= M) gmA = M - 1;

    float acc[2][8][4];
#pragma unroll
    for (int i = 0; i < 2; i++)
#pragma unroll
        for (int j = 0; j < 8; j++)
#pragma unroll
            for (int q = 0; q < 4; q++) acc[i][j][q] = 0.f;

    auto issue = [&](int it, int stg) {
        uint32_t sA = sbase + stg * STAGE_SZ;
        uint32_t sB = sA + A_SZ;
        const __half* asrc = Ah + (size_t)gmA * NF + it * 64 + aq * 32;
        uint32_t adst = sA + (uint32_t)(arow * PITCH + aq * 32) * 2;
#pragma unroll
        for (int j = 0; j < 4; j++) CP_ASYNC16(adst + j * 16, asrc + j * 8);
        const __half* bsrc = Bh + (size_t)(n0 + arow) * NF + it * 64 + aq * 32;
        uint32_t bdst = sB + (uint32_t)(arow * PITCH + aq * 32) * 2;
#pragma unroll
        for (int j = 0; j < 4; j++) CP_ASYNC16(bdst + j * 16, bsrc + j * 8);
        CP_COMMIT();
    };

    auto compute = [&](int stg) {
        uint32_t sA = sbase + stg * STAGE_SZ;
        uint32_t sB = sA + A_SZ;
#pragma unroll
        for (int ks = 0; ks < 4; ks++) {
            uint32_t af[2][4];
#pragma unroll
            for (int mt = 0; mt < 2; mt++) {
                uint32_t addr = sA +
                    (uint32_t)((wm + mt * 16 + (lane & 15)) * PITCH + ks * 16 +
                               ((lane >> 4) << 3)) * 2;
                LDSM_X4(af[mt][0], af[mt][1], af[mt][2], af[mt][3], addr);
            }
            uint32_t bf[4][4];
#pragma unroll
            for (int p = 0; p < 4; p++) {
                uint32_t addr = sB +
                    (uint32_t)((wn + p * 16 + ((lane >> 4) << 3) + (lane & 7)) * PITCH +
                               ks * 16 + ((lane >> 3) & 1) * 8) * 2;
                LDSM_X4(bf[p][0], bf[p][1], bf[p][2], bf[p][3], addr);
            }
#pragma unroll
            for (int mt = 0; mt < 2; mt++)
#pragma unroll
                for (int nt = 0; nt < 8; nt++)
                    mma_f16(acc[mt][nt], af[mt], &bf[nt >> 1][(nt & 1) * 2]);
        }
    };

    issue(0, 0);
    issue(1, 1);
    for (int it = 0; it < 4; it++) {
        if (it < 3) CP_WAIT1(); else CP_WAIT0();
        __syncthreads();
        compute(it % 3);
        if (it + 2 < 4) issue(it + 2, (it + 2) % 3);
    }

#pragma unroll
    for (int mt = 0; mt < 2; mt++) {
        int rr[2];
        rr[0] = m0 + wm + mt * 16 + (lane >> 2);
        rr[1] = rr[0] + 8;
#pragma unroll
        for (int nt = 0; nt < 8; nt++) {
            int n = n0 + wn + nt * 8 + (lane & 3) * 2;
            float b0 = __ldg(bias + n), b1 = __ldg(bias + n + 1);
#pragma unroll
            for (int h = 0; h < 2; h++) {
                int r = rr[h];
                if (r >= M) continue;
                __half ph[2] = {
                    __float2half_rn(fmaxf(acc[mt][nt][h * 2 + 0] + b0, 0.f)),
                    __float2half_rn(fmaxf(acc[mt][nt][h * 2 + 1] + b1, 0.f))};
                *(uint32_t*)(Cs + (size_t)r * NF + n) = *(uint32_t*)ph;
            }
        }
    }
}

// ---------------- fused final GEMM (N=40) + log_softmax, fp16 input ----------------
__global__ void __launch_bounds__(256) gemm40_lsm_kernel(
    const __half* __restrict__ A, const float* __restrict__ B,
    const float* __restrict__ bias, float* __restrict__ out, int M) {
    __shared__ float As[16][132];
    __shared__ float Bs[16][64];
    __shared__ float ls[128][44];
    int tid = threadIdx.x;
    int tn = tid % 16, tm = tid / 16;
    int m0 = blockIdx.x * 128;
    float acc[8][4];
#pragma unroll
    for (int i = 0; i < 8; i++)
#pragma unroll
        for (int j = 0; j < 4; j++) acc[i][j] = 0.f;

    for (int k0 = 0; k0 < NF; k0 += 16) {
        for (int i = tid; i < 128 * 16; i += 256) {
            int r = i >> 4, c = i & 15;
            int gm = m0 + r;
            As[c][r] = (gm < M) ? __half2float(A[(size_t)gm * NF + k0 + c]) : 0.f;
        }
        for (int i = tid; i < 16 * 64; i += 256) {
            int r = i >> 6, c = i & 63;
            Bs[r][c] = (c < 40) ? B[(size_t)(k0 + r) * 40 + c] : 0.f;
        }
        __syncthreads();
#pragma unroll
        for (int k = 0; k < 16; k++) {
            float av[8], bv[4];
#pragma unroll
            for (int i = 0; i < 8; i++) av[i] = As[k][tm * 8 + i];
#pragma unroll
            for (int j = 0; j < 4; j++) bv[j] = Bs[k][tn * 4 + j];
#pragma unroll
            for (int i = 0; i < 8; i++)
#pragma unroll
                for (int j = 0; j < 4; j++) acc[i][j] += av[i] * bv[j];
        }
        __syncthreads();
    }
#pragma unroll
    for (int i = 0; i < 8; i++)
#pragma unroll
        for (int j = 0; j < 4; j++) {
            int c = tn * 4 + j;
            if (c < 40) ls[tm * 8 + i][c] = acc[i][j] + bias[c];
        }
    __syncthreads();
    int wid = tid >> 5, lane = tid & 31;
    for (int i = 0; i < 16; i++) {
        int r = wid * 16 + i;
        int gr = m0 + r;
        if (gr >= M) continue;
        float v0 = ls[r][lane];
        float v1 = (lane < 8) ? ls[r][32 + lane] : -INFINITY;
        float m = fmaxf(v0, v1);
#pragma unroll
        for (int off = 16; off; off >>= 1) m = fmaxf(m, __shfl_xor_sync(0xffffffffu, m, off));
        float s = __expf(v0 - m) + ((lane < 8) ? __expf(v1 - m) : 0.f);
#pragma unroll
        for (int off = 16; off; off >>= 1) s += __shfl_xor_sync(0xffffffffu, s, off);
        float lse = m + __logf(s);
        out[(size_t)gr * 40 + lane] = v0 - lse;
        if (lane < 8) out[(size_t)gr * 40 + 32 + lane] = v1 - lse;
    }
}

// ---------------- launch ----------------
extern "C" void kernel_launch(void* const* d_in, const int* in_sizes, int n_in,
                              void* d_out, int out_size) {
    const float* x    = (const float*)d_in[0];
    const int*   erow = (const int*)d_in[1];
    const int*   ecol = (const int*)d_in[2];
    const float* ew   = (const float*)d_in[3];
    const float* W1 = (const float*)d_in[4];
    const float* b1 = (const float*)d_in[5];
    const float* W2 = (const float*)d_in[6];
    const float* b2 = (const float*)d_in[7];
    const float* W3 = (const float*)d_in[8];
    const float* b3 = (const float*)d_in[9];
    const float* W4 = (const float*)d_in[10];
    const float* b4 = (const float*)d_in[11];
    float* out = (float*)d_out;

    int E = in_sizes[1];
    int n = in_sizes[0] / NF;

    __half *wh, *h0, *h1;
    int* rowptr;
    cudaGetSymbolAddress((void**)&rowptr, g_rowptr);
    cudaGetSymbolAddress((void**)&wh, g_Wh);
    cudaGetSymbolAddress((void**)&h0, g_h0);
    cudaGetSymbolAddress((void**)&h1, g_h1);

    cudaFuncSetAttribute(fused_mlp2_kernel,
                         cudaFuncAttributeMaxDynamicSharedMemorySize, FUSED_SMEM);
    cudaFuncSetAttribute(gemm_f16_kernel,
                         cudaFuncAttributeMaxDynamicSharedMemorySize, GEMM_SMEM);

    int total4 = n * 64;
    int chN = (total4 > E) ? total4 : E;

    // CSR build + x conv
    cudaMemsetAsync(rowptr, 0, (size_t)(n + 1) * sizeof(int));
    conv_hist_kernel<<<(chN + 255) / 256, 256>>>(x, h0, erow, E, total4);   // 1
    scan_kernel<<<1, 1024>>>(n);                                            // 2
    scatter_kernel<<<(E / 2 + 255) / 256, 256>>>(erow, ecol, ew, E);        // 3

    int spmm_blocks = (n * 64 + 255) / 256;
    int fgrid = (n + 127) / 128;

    // h0g = x + spmm(x): h0 -> h1                       [4th kernel: profiled]
    spmm_f16_kernel<<<spmm_blocks, 256>>>(h0, h1, n);

    // weight prep (all 3 layers)
    dim3 pgrid(256, 3);
    prep_w_f16<<<pgrid, 256>>>(W1, W2, W3, wh);

    // h2g = relu(relu(h0g@W1+b1)@W2+b2): h1 -> h0
    fused_mlp2_kernel<<<fgrid, 512, FUSED_SMEM>>>(
        h1, wh + 0 * (size_t)NF * NF, b1, wh + 1 * (size_t)NF * NF, b2, h0, n);
    // h3g = h2g + spmm(h2g): h0 -> h1
    spmm_f16_kernel<<<spmm_blocks, 256>>>(h0, h1, n);
    // h4g = relu(h3g @ W3 + b3): h1 -> h0 (fp16)
    dim3 ggrid(fgrid, 2);
    gemm_f16_kernel<<<ggrid, 256, GEMM_SMEM>>>(h1, wh + 2 * (size_t)NF * NF, b3, h0, n);
    // logits + log_softmax -> d_out
    gemm40_lsm_kernel<<<fgrid, 256>>>(h0, W4, b4, out, n);
}

// round 12
// speedup vs baseline: 1.7843x; 1.1880x over previous
#include <cuda_runtime.h>
#include <cuda_fp16.h>
#include <math.h>
#include <stdint.h>

#define NNODES 100000
#define NEDGES 3200000
#define NF 256

// ---------------- scratch (device globals; no allocs allowed) ----------------
__device__ __half g_h0[(size_t)NNODES * NF];            // fp16 ping
__device__ __half g_h1[(size_t)NNODES * NF];            // fp16 pong
__device__ int   g_rowptr[NNODES + 1];
__device__ int   g_cursor[NNODES];
__device__ uint2 g_cw[NEDGES];                          // packed {col*512 (byte off), weight}
__device__ __half g_Wh[3][NF * NF];                     // fp16 weights, [N][K] K-major
__device__ __half g_W4p[64 * NF];                       // W4 padded [64][256] K-major fp16

// ---------------- helpers ----------------
__device__ __forceinline__ uint32_t smem_u32(const void* p) {
    uint32_t a;
    asm("{ .reg .u64 t; cvta.to.shared.u64 t, %1; cvt.u32.u64 %0, t; }" : "=r"(a) : "l"(p));
    return a;
}

#define LDSM_X4(r0, r1, r2, r3, addr) \
    asm volatile("ldmatrix.sync.aligned.m8n8.x4.shared.b16 {%0,%1,%2,%3}, [%4];" \
                 : "=r"(r0), "=r"(r1), "=r"(r2), "=r"(r3) : "r"(addr))

__device__ __forceinline__ void mma_f16(float* d, const uint32_t* a, const uint32_t* b) {
    asm volatile(
        "mma.sync.aligned.m16n8k16.row.col.f32.f16.f16.f32 "
        "{%0,%1,%2,%3}, {%4,%5,%6,%7}, {%8,%9}, {%0,%1,%2,%3};"
        : "+f"(d[0]), "+f"(d[1]), "+f"(d[2]), "+f"(d[3])
        : "r"(a[0]), "r"(a[1]), "r"(a[2]), "r"(a[3]), "r"(b[0]), "r"(b[1]));
}

#define CP_ASYNC16(dst, src) \
    asm volatile("cp.async.cg.shared.global [%0], [%1], 16;" :: "r"(dst), "l"(src))
#define CP_COMMIT() asm volatile("cp.async.commit_group;")
#define CP_WAIT1() asm volatile("cp.async.wait_group 1;")
#define CP_WAIT0() asm volatile("cp.async.wait_group 0;")

// ---------------- merged: x -> fp16 copy + degree histogram ----------------
__global__ void conv_hist_kernel(const float* __restrict__ x, __half* __restrict__ xh,
                                 const int* __restrict__ erow, int E, int total4) {
    int i = blockIdx.x * blockDim.x + threadIdx.x;
    if (i < total4) {
        float4 v = ((const float4*)x)[i];
        __half h[4] = {__float2half_rn(v.x), __float2half_rn(v.y),
                       __float2half_rn(v.z), __float2half_rn(v.w)};
        *(uint2*)(xh + (size_t)i * 4) = *(uint2*)h;
    }
    if (i < E) atomicAdd(&g_rowptr[erow[i]], 1);
}

__global__ void scan_kernel(int n) {
    __shared__ int part[1024];
    int t = threadIdx.x;
    int CH = (n + 1023) / 1024;
    int beg = t * CH;
    int end = min(beg + CH, n);
    int s = 0;
    for (int i = beg; i < end; i++) s += g_rowptr[i];
    part[t] = s;
    __syncthreads();
    for (int off = 1; off < 1024; off <<= 1) {
        int v = (t >= off) ? part[t - off] : 0;
        __syncthreads();
        part[t] += v;
        __syncthreads();
    }
    int base = (t == 0) ? 0 : part[t - 1];
    int run = base;
    for (int i = beg; i < end; i++) {
        int c = g_rowptr[i];
        g_rowptr[i] = run;
        g_cursor[i] = run;
        run += c;
    }
    if (t == 1023) g_rowptr[n] = part[1023];
}

__global__ void scatter_kernel(const int* __restrict__ erow,
                               const int* __restrict__ ecol,
                               const float* __restrict__ ew, int E) {
    int i = (blockIdx.x * blockDim.x + threadIdx.x) * 2;
#pragma unroll
    for (int j = 0; j < 2; j++) {
        if (i + j < E) {
            int r = erow[i + j];
            int pos = atomicAdd(&g_cursor[r], 1);
            uint2 cw;
            cw.x = (uint32_t)ecol[i + j] * 512u;   // premultiplied byte row offset
            cw.y = __float_as_uint(ew[i + j]);
            g_cw[pos] = cw;
        }
    }
}

// ---------------- SPMM (fp16 gather, paired edges, 32-bit offsets) ----------------
__global__ void spmm_f16_kernel(const __half* __restrict__ src,
                                __half* __restrict__ dst, int n) {
    int gw = (blockIdx.x * blockDim.x + threadIdx.x) >> 5;
    int row = gw >> 1;
    if (row >= n) return;
    int f4 = (gw & 1) * 32 + (threadIdx.x & 31);
    uint32_t foff = (uint32_t)f4 * 8;
    const char* sp = (const char*)src;

    uint2 rv = __ldg((const uint2*)(sp + (size_t)row * 512 + foff));
    float2 p0 = __half22float2(*(__half2*)&rv.x);
    float2 p1 = __half22float2(*(__half2*)&rv.y);
    float ax = p0.x, ay = p0.y, az = p1.x, aw = p1.y;

    int beg = g_rowptr[row], end = g_rowptr[row + 1];
    int e = beg;

    auto acc1 = [&](uint32_t coff, uint32_t wbits) {
        float w = __uint_as_float(wbits);
        uint2 v = __ldg((const uint2*)(sp + (size_t)(coff + foff)));
        float2 a = __half22float2(*(__half2*)&v.x);
        float2 b = __half22float2(*(__half2*)&v.y);
        ax += w * a.x; ay += w * a.y; az += w * b.x; aw += w * b.y;
    };

    if ((e & 1) && e < end) {
        uint2 cw = __ldg(&g_cw[e]);
        acc1(cw.x, cw.y);
        e++;
    }
    const uint4* cw4 = (const uint4*)g_cw;
    for (; e + 8 <= end; e += 8) {
        uint4 q0 = __ldg(&cw4[(e >> 1) + 0]);
        uint4 q1 = __ldg(&cw4[(e >> 1) + 1]);
        uint4 q2 = __ldg(&cw4[(e >> 1) + 2]);
        uint4 q3 = __ldg(&cw4[(e >> 1) + 3]);
        acc1(q0.x, q0.y); acc1(q0.z, q0.w);
        acc1(q1.x, q1.y); acc1(q1.z, q1.w);
        acc1(q2.x, q2.y); acc1(q2.z, q2.w);
        acc1(q3.x, q3.y); acc1(q3.z, q3.w);
    }
    for (; e + 2 <= end; e += 2) {
        uint4 q = __ldg(&cw4[e >> 1]);
        acc1(q.x, q.y); acc1(q.z, q.w);
    }
    if (e < end) {
        uint2 cw = __ldg(&g_cw[e]);
        acc1(cw.x, cw.y);
    }

    __half o[4] = {__float2half_rn(ax), __float2half_rn(ay),
                   __float2half_rn(az), __float2half_rn(aw)};
    *(uint2*)(dst + (size_t)row * 256 + f4 * 4) = *(uint2*)o;
}

// ---------------- weight prep: W1-3 transpose + W4 padded ----------------
__global__ void prep_w_f16(const float* __restrict__ W1, const float* __restrict__ W2,
                           const float* __restrict__ W3, const float* __restrict__ W4,
                           __half* __restrict__ Bh, __half* __restrict__ W4p) {
    int n = blockIdx.x;
    int k = threadIdx.x;
    int l = blockIdx.y;
    if (l < 3) {
        const float* W = (l == 0) ? W1 : (l == 1) ? W2 : W3;
        Bh[(size_t)l * NF * NF + (size_t)n * NF + k] = __float2half_rn(W[(size_t)k * NF + n]);
    } else if (n < 64) {
        W4p[(size_t)n * NF + k] = (n < 40) ? __float2half_rn(W4[(size_t)k * 40 + n])
                                           : __ushort_as_half((unsigned short)0);
    }
}

// ---------------- shared tile layout ----------------
#define PITCH 72
#define A_SZ1 (128 * PITCH * 2)          // 18432
#define B_SZ1 (256 * PITCH * 2)          // 36864
#define STAGE1 (A_SZ1 + B_SZ1)           // 55296
#define FUSED_SMEM (3 * STAGE1)          // 165888
#define H1_PITCH 264
#define H1_OFF 0                         // 128*264*2 = 67584
#define B2_OFF0 68608
#define B2_OFF1 (68608 + 36864)
#define BIAS_OFF (B2_OFF1 + 36864)       // 142336; written only AFTER phase 1

// ---------------- fused GEMM1+GEMM2 ----------------
__global__ void __launch_bounds__(512) fused_mlp2_kernel(
    const __half* __restrict__ Ah, const __half* __restrict__ W1h,
    const float* __restrict__ b1, const __half* __restrict__ W2h,
    const float* __restrict__ b2, __half* __restrict__ Out, int M) {
    extern __shared__ char smem[];
    uint32_t sbase = smem_u32(smem);
    uint32_t sh1 = sbase + H1_OFF;

    int tid = threadIdx.x, lane = tid & 31, wid = tid >> 5;
    int m0 = blockIdx.x * 128;
    int wm = (wid >> 2) * 32;
    int wn = (wid & 3) * 64;

    int arow = tid >> 2, aq = tid & 3;
    int gmA = m0 + arow; if (gmA >= M) gmA = M - 1;
    int brow = tid >> 1, bh = tid & 1;

    float acc[2][8][4];
#pragma unroll
    for (int i = 0; i < 2; i++)
#pragma unroll
        for (int j = 0; j < 8; j++)
#pragma unroll
            for (int q = 0; q < 4; q++) acc[i][j][q] = 0.f;

    auto issue1 = [&](int it, int stg) {
        uint32_t sA = sbase + stg * STAGE1;
        uint32_t sB = sA + A_SZ1;
        const __half* asrc = Ah + (size_t)gmA * NF + it * 64 + aq * 16;
        uint32_t adst = sA + (uint32_t)(arow * PITCH + aq * 16) * 2;
        CP_ASYNC16(adst, asrc);
        CP_ASYNC16(adst + 16, asrc + 8);
        const __half* bsrc = W1h + (size_t)brow * NF + it * 64 + bh * 32;
        uint32_t bdst = sB + (uint32_t)(brow * PITCH + bh * 32) * 2;
#pragma unroll
        for (int j = 0; j < 4; j++) CP_ASYNC16(bdst + j * 16, bsrc + j * 8);
        CP_COMMIT();
    };

    auto compute1 = [&](int stg) {
        uint32_t sA = sbase + stg * STAGE1;
        uint32_t sB = sA + A_SZ1;
#pragma unroll
        for (int ks = 0; ks < 4; ks++) {
            uint32_t af[2][4];
#pragma unroll
            for (int mt = 0; mt < 2; mt++) {
                uint32_t addr = sA +
                    (uint32_t)((wm + mt * 16 + (lane & 15)) * PITCH + ks * 16 +
                               ((lane >> 4) << 3)) * 2;
                LDSM_X4(af[mt][0], af[mt][1], af[mt][2], af[mt][3], addr);
            }
            uint32_t bf[4][4];
#pragma unroll
            for (int p = 0; p < 4; p++) {
                uint32_t addr = sB +
                    (uint32_t)((wn + p * 16 + ((lane >> 4) << 3) + (lane & 7)) * PITCH +
                               ks * 16 + ((lane >> 3) & 1) * 8) * 2;
                LDSM_X4(bf[p][0], bf[p][1], bf[p][2], bf[p][3], addr);
            }
#pragma unroll
            for (int mt = 0; mt < 2; mt++)
#pragma unroll
                for (int nt = 0; nt < 8; nt++)
                    mma_f16(acc[mt][nt], af[mt], &bf[nt >> 1][(nt & 1) * 2]);
        }
    };

    issue1(0, 0);
    issue1(1, 1);
    for (int it = 0; it < 4; it++) {
        if (it < 3) CP_WAIT1(); else CP_WAIT0();
        __syncthreads();
        compute1(it % 3);
        if (it + 2 < 4) issue1(it + 2, (it + 2) % 3);
    }
    __syncthreads();

    // h1 = relu(acc + b1) -> smem; reset acc
#pragma unroll
    for (int mt = 0; mt < 2; mt++) {
        int r0 = wm + mt * 16 + (lane >> 2);
#pragma unroll
        for (int nt = 0; nt < 8; nt++) {
            int n = wn + nt * 8 + (lane & 3) * 2;
            float c0 = __ldg(b1 + n), c1 = __ldg(b1 + n + 1);
#pragma unroll
            for (int h = 0; h < 2; h++) {
                int r = r0 + h * 8;
                __half ph[2] = {
                    __float2half_rn(fmaxf(acc[mt][nt][h * 2 + 0] + c0, 0.f)),
                    __float2half_rn(fmaxf(acc[mt][nt][h * 2 + 1] + c1, 0.f))};
                asm volatile("st.shared.b32 [%0], %1;"
                             :: "r"(sh1 + (uint32_t)(r * H1_PITCH + n) * 2),
                                "r"(*(uint32_t*)ph));
                acc[mt][nt][h * 2 + 0] = 0.f;
                acc[mt][nt][h * 2 + 1] = 0.f;
            }
        }
    }
    __syncthreads();

    // phase 2: h1(smem) @ W2
    uint32_t sB2[2] = {sbase + B2_OFF0, sbase + B2_OFF1};

    auto issue2 = [&](int kc, int buf) {
        const __half* bsrc = W2h + (size_t)brow * NF + kc * 64 + bh * 32;
        uint32_t bdst = sB2[buf] + (uint32_t)(brow * PITCH + bh * 32) * 2;
#pragma unroll
        for (int j = 0; j < 4; j++) CP_ASYNC16(bdst + j * 16, bsrc + j * 8);
        CP_COMMIT();
    };

    auto compute2 = [&](int kc, int buf) {
        uint32_t sB = sB2[buf];
#pragma unroll
        for (int ks = 0; ks < 4; ks++) {
            uint32_t af[2][4];
#pragma unroll
            for (int mt = 0; mt < 2; mt++) {
                uint32_t addr = sh1 +
                    (uint32_t)((wm + mt * 16 + (lane & 15)) * H1_PITCH + kc * 64 +
                               ks * 16 + ((lane >> 4) << 3)) * 2;
                LDSM_X4(af[mt][0], af[mt][1], af[mt][2], af[mt][3], addr);
            }
            uint32_t bf[4][4];
#pragma unroll
            for (int p = 0; p < 4; p++) {
                uint32_t addr = sB +
                    (uint32_t)((wn + p * 16 + ((lane >> 4) << 3) + (lane & 7)) * PITCH +
                               ks * 16 + ((lane >> 3) & 1) * 8) * 2;
                LDSM_X4(bf[p][0], bf[p][1], bf[p][2], bf[p][3], addr);
            }
#pragma unroll
            for (int mt = 0; mt < 2; mt++)
#pragma unroll
                for (int nt = 0; nt < 8; nt++)
                    mma_f16(acc[mt][nt], af[mt], &bf[nt >> 1][(nt & 1) * 2]);
        }
    };

    issue2(0, 0);
    issue2(1, 1);
    for (int kc = 0; kc < 4; kc++) {
        if (kc < 3) CP_WAIT1(); else CP_WAIT0();
        __syncthreads();
        compute2(kc, kc & 1);
        if (kc + 2 < 4) {
            __syncthreads();
            issue2(kc + 2, kc & 1);
        }
    }

    // epilogue: h2 -> gmem fp16
#pragma unroll
    for (int mt = 0; mt < 2; mt++) {
        int rr[2];
        rr[0] = m0 + wm + mt * 16 + (lane >> 2);
        rr[1] = rr[0] + 8;
#pragma unroll
        for (int nt = 0; nt < 8; nt++) {
            int n = wn + nt * 8 + (lane & 3) * 2;
            float c0 = __ldg(b2 + n), c1 = __ldg(b2 + n + 1);
#pragma unroll
            for (int h = 0; h < 2; h++) {
                int r = rr[h];
                if (r >= M) continue;
                __half ph[2] = {
                    __float2half_rn(fmaxf(acc[mt][nt][h * 2 + 0] + c0, 0.f)),
                    __float2half_rn(fmaxf(acc[mt][nt][h * 2 + 1] + c1, 0.f))};
                *(uint32_t*)(Out + (size_t)r * NF + n) = *(uint32_t*)ph;
            }
        }
    }
}

// ---------------- fused GEMM3 + final GEMM(40) + log_softmax ----------------
__global__ void __launch_bounds__(512) fused_out_kernel(
    const __half* __restrict__ Ah, const __half* __restrict__ W3h,
    const float* __restrict__ b3, const __half* __restrict__ W4p,
    const float* __restrict__ b4, float* __restrict__ Out, int M) {
    extern __shared__ char smem[];
    uint32_t sbase = smem_u32(smem);
    uint32_t sh1 = sbase + H1_OFF;

    int tid = threadIdx.x, lane = tid & 31, wid = tid >> 5;
    int m0 = blockIdx.x * 128;
    int wm = (wid >> 2) * 32;
    int wn = (wid & 3) * 64;

    int arow = tid >> 2, aq = tid & 3;
    int gmA = m0 + arow; if (gmA >= M) gmA = M - 1;
    int brow = tid >> 1, bh = tid & 1;

    float* sbias = (float*)(smem + BIAS_OFF);   // written AFTER phase 1 (region is
                                                // clobbered by phase-1 stage buffers)

    float acc[2][8][4];
#pragma unroll
    for (int i = 0; i < 2; i++)
#pragma unroll
        for (int j = 0; j < 8; j++)
#pragma unroll
            for (int q = 0; q < 4; q++) acc[i][j][q] = 0.f;

    auto issue1 = [&](int it, int stg) {
        uint32_t sA = sbase + stg * STAGE1;
        uint32_t sB = sA + A_SZ1;
        const __half* asrc = Ah + (size_t)gmA * NF + it * 64 + aq * 16;
        uint32_t adst = sA + (uint32_t)(arow * PITCH + aq * 16) * 2;
        CP_ASYNC16(adst, asrc);
        CP_ASYNC16(adst + 16, asrc + 8);
        const __half* bsrc = W3h + (size_t)brow * NF + it * 64 + bh * 32;
        uint32_t bdst = sB + (uint32_t)(brow * PITCH + bh * 32) * 2;
#pragma unroll
        for (int j = 0; j < 4; j++) CP_ASYNC16(bdst + j * 16, bsrc + j * 8);
        CP_COMMIT();
    };

    auto compute1 = [&](int stg) {
        uint32_t sA = sbase + stg * STAGE1;
        uint32_t sB = sA + A_SZ1;
#pragma unroll
        for (int ks = 0; ks < 4; ks++) {
            uint32_t af[2][4];
#pragma unroll
            for (int mt = 0; mt < 2; mt++) {
                uint32_t addr = sA +
                    (uint32_t)((wm + mt * 16 + (lane & 15)) * PITCH + ks * 16 +
                               ((lane >> 4) << 3)) * 2;
                LDSM_X4(af[mt][0], af[mt][1], af[mt][2], af[mt][3], addr);
            }
            uint32_t bf[4][4];
#pragma unroll
            for (int p = 0; p < 4; p++) {
                uint32_t addr = sB +
                    (uint32_t)((wn + p * 16 + ((lane >> 4) << 3) + (lane & 7)) * PITCH +
                               ks * 16 + ((lane >> 3) & 1) * 8) * 2;
                LDSM_X4(bf[p][0], bf[p][1], bf[p][2], bf[p][3], addr);
            }
#pragma unroll
            for (int mt = 0; mt < 2; mt++)
#pragma unroll
                for (int nt = 0; nt < 8; nt++)
                    mma_f16(acc[mt][nt], af[mt], &bf[nt >> 1][(nt & 1) * 2]);
        }
    };

    issue1(0, 0);
    issue1(1, 1);
    for (int it = 0; it < 4; it++) {
        if (it < 3) CP_WAIT1(); else CP_WAIT0();
        __syncthreads();
        compute1(it % 3);
        if (it + 2 < 4) issue1(it + 2, (it + 2) % 3);
    }
    __syncthreads();

    // h4 = relu(acc + b3) -> smem; also write padded b4 bias now (stage bufs dead)
    if (tid < 64) sbias[tid] = (tid < 40) ? b4[tid] : -1e30f;
#pragma unroll
    for (int mt = 0; mt < 2; mt++) {
        int r0 = wm + mt * 16 + (lane >> 2);
#pragma unroll
        for (int nt = 0; nt < 8; nt++) {
            int n = wn + nt * 8 + (lane & 3) * 2;
            float c0 = __ldg(b3 + n), c1 = __ldg(b3 + n + 1);
#pragma unroll
            for (int h = 0; h < 2; h++) {
                int r = r0 + h * 8;
                __half ph[2] = {
                    __float2half_rn(fmaxf(acc[mt][nt][h * 2 + 0] + c0, 0.f)),
                    __float2half_rn(fmaxf(acc[mt][nt][h * 2 + 1] + c1, 0.f))};
                asm volatile("st.shared.b32 [%0], %1;"
                             :: "r"(sh1 + (uint32_t)(r * H1_PITCH + n) * 2),
                                "r"(*(uint32_t*)ph));
            }
        }
    }

    // load W4pad [64 rows][256] into B2_OFF0 (4 k-chunks, PITCH layout)
    uint32_t sW4 = sbase + B2_OFF0;
    if (tid < 128) {
        int br = tid >> 1, bq = tid & 1;
#pragma unroll
        for (int kc = 0; kc < 4; kc++) {
            const __half* bsrc = W4p + (size_t)br * NF + kc * 64 + bq * 32;
            uint32_t bdst = sW4 + (uint32_t)(kc * 64 * PITCH + br * PITCH + bq * 32) * 2;
#pragma unroll
            for (int j = 0; j < 4; j++) CP_ASYNC16(bdst + j * 16, bsrc + j * 8);
        }
    }
    CP_COMMIT();
    CP_WAIT0();
    __syncthreads();

    // phase 2: logits = h4(smem) @ W4pad; warps 0..7, warp w = rows w*16..w*16+16
    if (wid < 8) {
        float acc2[8][4];
#pragma unroll
        for (int j = 0; j < 8; j++)
#pragma unroll
            for (int q = 0; q < 4; q++) acc2[j][q] = 0.f;

#pragma unroll
        for (int kc = 0; kc < 4; kc++) {
#pragma unroll
            for (int ks = 0; ks < 4; ks++) {
                uint32_t af[4];
                uint32_t aaddr = sh1 +
                    (uint32_t)((wid * 16 + (lane & 15)) * H1_PITCH + kc * 64 +
                               ks * 16 + ((lane >> 4) << 3)) * 2;
                LDSM_X4(af[0], af[1], af[2], af[3], aaddr);
                uint32_t bf[4][4];
#pragma unroll
                for (int p = 0; p < 4; p++) {
                    uint32_t baddr = sW4 +
                        (uint32_t)(kc * 64 * PITCH +
                                   (p * 16 + ((lane >> 4) << 3) + (lane & 7)) * PITCH +
                                   ks * 16 + ((lane >> 3) & 1) * 8) * 2;
                    LDSM_X4(bf[p][0], bf[p][1], bf[p][2], bf[p][3], baddr);
                }
#pragma unroll
                for (int nt = 0; nt < 8; nt++)
                    mma_f16(acc2[nt], af, &bf[nt >> 1][(nt & 1) * 2]);
            }
        }

        // log_softmax: row gr = m0 + wid*16 + (lane>>2) + h*8
#pragma unroll
        for (int h = 0; h < 2; h++) {
            int gr = m0 + wid * 16 + (lane >> 2) + h * 8;
            float lg[16];
            float mx = -1e30f;
#pragma unroll
            for (int nt = 0; nt < 8; nt++) {
                int c = nt * 8 + (lane & 3) * 2;
                lg[nt * 2 + 0] = acc2[nt][h * 2 + 0] + sbias[c];
                lg[nt * 2 + 1] = acc2[nt][h * 2 + 1] + sbias[c + 1];
                mx = fmaxf(mx, fmaxf(lg[nt * 2], lg[nt * 2 + 1]));
            }
            mx = fmaxf(mx, __shfl_xor_sync(0xffffffffu, mx, 1));
            mx = fmaxf(mx, __shfl_xor_sync(0xffffffffu, mx, 2));
            float s = 0.f;
#pragma unroll
            for (int q = 0; q < 16; q++) s += __expf(lg[q] - mx);
            s += __shfl_xor_sync(0xffffffffu, s, 1);
            s += __shfl_xor_sync(0xffffffffu, s, 2);
            float lse = mx + __logf(s);
            if (gr < M) {
#pragma unroll
                for (int nt = 0; nt < 5; nt++) {
                    int c = nt * 8 + (lane & 3) * 2;
                    if (c < 40) {
                        float2 o;
                        o.x = lg[nt * 2 + 0] - lse;
                        o.y = lg[nt * 2 + 1] - lse;
                        *(float2*)(Out + (size_t)gr * 40 + c) = o;
                    }
                }
            }
        }
    }
}

// ---------------- launch ----------------
extern "C" void kernel_launch(void* const* d_in, const int* in_sizes, int n_in,
                              void* d_out, int out_size) {
    const float* x    = (const float*)d_in[0];
    const int*   erow = (const int*)d_in[1];
    const int*   ecol = (const int*)d_in[2];
    const float* ew   = (const float*)d_in[3];
    const float* W1 = (const float*)d_in[4];
    const float* b1 = (const float*)d_in[5];
    const float* W2 = (const float*)d_in[6];
    const float* b2 = (const float*)d_in[7];
    const float* W3 = (const float*)d_in[8];
    const float* b3 = (const float*)d_in[9];
    const float* W4 = (const float*)d_in[10];
    const float* b4 = (const float*)d_in[11];
    float* out = (float*)d_out;

    int E = in_sizes[1];
    int n = in_sizes[0] / NF;

    __half *wh, *h0, *h1, *w4p;
    int* rowptr;
    cudaGetSymbolAddress((void**)&rowptr, g_rowptr);
    cudaGetSymbolAddress((void**)&wh, g_Wh);
    cudaGetSymbolAddress((void**)&h0, g_h0);
    cudaGetSymbolAddress((void**)&h1, g_h1);
    cudaGetSymbolAddress((void**)&w4p, g_W4p);

    cudaFuncSetAttribute(fused_mlp2_kernel,
                         cudaFuncAttributeMaxDynamicSharedMemorySize, FUSED_SMEM);
    cudaFuncSetAttribute(fused_out_kernel,
                         cudaFuncAttributeMaxDynamicSharedMemorySize, FUSED_SMEM);

    int total4 = n * 64;
    int chN = (total4 > E) ? total4 : E;

    // CSR build + x conv
    cudaMemsetAsync(rowptr, 0, (size_t)(n + 1) * sizeof(int));
    conv_hist_kernel<<<(chN + 255) / 256, 256>>>(x, h0, erow, E, total4);   // 1
    scan_kernel<<<1, 1024>>>(n);                                            // 2
    scatter_kernel<<<(E / 2 + 255) / 256, 256>>>(erow, ecol, ew, E);        // 3

    int spmm_blocks = (n * 64 + 255) / 256;
    int fgrid = (n + 127) / 128;

    // h0g = x + spmm(x): h0 -> h1                       [4th kernel: profiled]
    spmm_f16_kernel<<<spmm_blocks, 256>>>(h0, h1, n);

    // weight prep (W1-3 transpose + W4 pad)
    dim3 pgrid(256, 4);
    prep_w_f16<<<pgrid, 256>>>(W1, W2, W3, W4, wh, w4p);

    // h2g = relu(relu(h0g@W1+b1)@W2+b2): h1 -> h0
    fused_mlp2_kernel<<<fgrid, 512, FUSED_SMEM>>>(
        h1, wh + 0 * (size_t)NF * NF, b1, wh + 1 * (size_t)NF * NF, b2, h0, n);
    // h3g = h2g + spmm(h2g): h0 -> h1
    spmm_f16_kernel<<<spmm_blocks, 256>>>(h0, h1, n);
    // out = log_softmax(relu(h3g@W3+b3) @ W4 + b4)
    fused_out_kernel<<<fgrid, 512, FUSED_SMEM>>>(
        h1, wh + 2 * (size_t)NF * NF, b3, w4p, b4, out, n);
}

// round 13
// speedup vs baseline: 2.0005x; 1.1212x over previous
#include <cuda_runtime.h>
#include <cuda_fp16.h>
#include <math.h>
#include <stdint.h>

#define NNODES 100000
#define NEDGES 3200000
#define NF 256

// ---------------- scratch (device globals; no allocs allowed) ----------------
__device__ __half g_h0[(size_t)NNODES * NF];            // fp16 ping
__device__ __half g_h1[(size_t)NNODES * NF];            // fp16 pong
__device__ int   g_rowptr[NNODES + 1];
__device__ int   g_cursor[NNODES];
__device__ uint2 g_cw[NEDGES];                          // packed {col*512 (byte off), weight}
__device__ __half g_Wh[3][NF * NF];                     // fp16 weights, [N][K] K-major
__device__ __half g_W4p[64 * NF];                       // W4 padded [64][256] K-major fp16

// ---------------- helpers ----------------
__device__ __forceinline__ uint32_t smem_u32(const void* p) {
    uint32_t a;
    asm("{ .reg .u64 t; cvta.to.shared.u64 t, %1; cvt.u32.u64 %0, t; }" : "=r"(a) : "l"(p));
    return a;
}

#define LDSM_X4(r0, r1, r2, r3, addr) \
    asm volatile("ldmatrix.sync.aligned.m8n8.x4.shared.b16 {%0,%1,%2,%3}, [%4];" \
                 : "=r"(r0), "=r"(r1), "=r"(r2), "=r"(r3) : "r"(addr))

__device__ __forceinline__ void mma_f16(float* d, const uint32_t* a, const uint32_t* b) {
    asm volatile(
        "mma.sync.aligned.m16n8k16.row.col.f32.f16.f16.f32 "
        "{%0,%1,%2,%3}, {%4,%5,%6,%7}, {%8,%9}, {%0,%1,%2,%3};"
        : "+f"(d[0]), "+f"(d[1]), "+f"(d[2]), "+f"(d[3])
        : "r"(a[0]), "r"(a[1]), "r"(a[2]), "r"(a[3]), "r"(b[0]), "r"(b[1]));
}

#define CP_ASYNC16(dst, src) \
    asm volatile("cp.async.cg.shared.global [%0], [%1], 16;" :: "r"(dst), "l"(src))
#define CP_COMMIT() asm volatile("cp.async.commit_group;")
#define CP_WAIT1() asm volatile("cp.async.wait_group 1;")
#define CP_WAIT0() asm volatile("cp.async.wait_group 0;")

// ---------------- merged: x -> fp16 copy + degree histogram (x2 unroll) ----------------
__global__ void conv_hist_kernel(const float* __restrict__ x, __half* __restrict__ xh,
                                 const int* __restrict__ erow, int E, int total4) {
    int i = (blockIdx.x * blockDim.x + threadIdx.x) * 2;
#pragma unroll
    for (int j = 0; j < 2; j++) {
        int k = i + j;
        if (k < total4) {
            float4 v = ((const float4*)x)[k];
            __half h[4] = {__float2half_rn(v.x), __float2half_rn(v.y),
                           __float2half_rn(v.z), __float2half_rn(v.w)};
            *(uint2*)(xh + (size_t)k * 4) = *(uint2*)h;
        }
        if (k < E) atomicAdd(&g_rowptr[erow[k]], 1);
    }
}

__global__ void scan_kernel(int n) {
    __shared__ int part[1024];
    int t = threadIdx.x;
    int CH = (n + 1023) / 1024;
    int beg = t * CH;
    int end = min(beg + CH, n);
    int s = 0;
    for (int i = beg; i < end; i++) s += g_rowptr[i];
    part[t] = s;
    __syncthreads();
    for (int off = 1; off < 1024; off <<= 1) {
        int v = (t >= off) ? part[t - off] : 0;
        __syncthreads();
        part[t] += v;
        __syncthreads();
    }
    int base = (t == 0) ? 0 : part[t - 1];
    int run = base;
    for (int i = beg; i < end; i++) {
        int c = g_rowptr[i];
        g_rowptr[i] = run;
        g_cursor[i] = run;
        run += c;
    }
    if (t == 1023) g_rowptr[n] = part[1023];
}

// unroll x4: four independent atomic chains per thread
__global__ void scatter_kernel(const int* __restrict__ erow,
                               const int* __restrict__ ecol,
                               const float* __restrict__ ew, int E) {
    int i = (blockIdx.x * blockDim.x + threadIdx.x) * 4;
#pragma unroll
    for (int j = 0; j < 4; j++) {
        if (i + j < E) {
            int r = erow[i + j];
            int pos = atomicAdd(&g_cursor[r], 1);
            uint2 cw;
            cw.x = (uint32_t)ecol[i + j] * 512u;   // premultiplied byte row offset
            cw.y = __float_as_uint(ew[i + j]);
            g_cw[pos] = cw;
        }
    }
}

// ---------------- SPMM: one warp per row, uint4 gathers ----------------
__global__ void spmm_f16_kernel(const __half* __restrict__ src,
                                __half* __restrict__ dst, int n) {
    int row = (blockIdx.x * blockDim.x + threadIdx.x) >> 5;
    if (row >= n) return;
    int lane = threadIdx.x & 31;
    uint32_t foff = (uint32_t)lane * 16;   // 16B per lane, warp covers 512B row
    const char* sp = (const char*)src;

    uint4 rv = __ldg((const uint4*)(sp + (size_t)row * 512 + foff));
    float2 q0 = __half22float2(*(__half2*)&rv.x);
    float2 q1 = __half22float2(*(__half2*)&rv.y);
    float2 q2 = __half22float2(*(__half2*)&rv.z);
    float2 q3 = __half22float2(*(__half2*)&rv.w);
    float a0 = q0.x, a1 = q0.y, a2 = q1.x, a3 = q1.y;
    float a4 = q2.x, a5 = q2.y, a6 = q3.x, a7 = q3.y;

    int beg = g_rowptr[row], end = g_rowptr[row + 1];
    int e = beg;

    auto acc1 = [&](uint32_t coff, uint32_t wbits) {
        float w = __uint_as_float(wbits);
        uint4 v = __ldg((const uint4*)(sp + (size_t)(coff + foff)));
        float2 p0 = __half22float2(*(__half2*)&v.x);
        float2 p1 = __half22float2(*(__half2*)&v.y);
        float2 p2 = __half22float2(*(__half2*)&v.z);
        float2 p3 = __half22float2(*(__half2*)&v.w);
        a0 += w * p0.x; a1 += w * p0.y; a2 += w * p1.x; a3 += w * p1.y;
        a4 += w * p2.x; a5 += w * p2.y; a6 += w * p3.x; a7 += w * p3.y;
    };

    if ((e & 1) && e < end) {
        uint2 cw = __ldg(&g_cw[e]);
        acc1(cw.x, cw.y);
        e++;
    }
    const uint4* cw4 = (const uint4*)g_cw;
    for (; e + 8 <= end; e += 8) {
        uint4 c0 = __ldg(&cw4[(e >> 1) + 0]);
        uint4 c1 = __ldg(&cw4[(e >> 1) + 1]);
        uint4 c2 = __ldg(&cw4[(e >> 1) + 2]);
        uint4 c3 = __ldg(&cw4[(e >> 1) + 3]);
        acc1(c0.x, c0.y); acc1(c0.z, c0.w);
        acc1(c1.x, c1.y); acc1(c1.z, c1.w);
        acc1(c2.x, c2.y); acc1(c2.z, c2.w);
        acc1(c3.x, c3.y); acc1(c3.z, c3.w);
    }
    for (; e + 2 <= end; e += 2) {
        uint4 c = __ldg(&cw4[e >> 1]);
        acc1(c.x, c.y); acc1(c.z, c.w);
    }
    if (e < end) {
        uint2 cw = __ldg(&g_cw[e]);
        acc1(cw.x, cw.y);
    }

    __half o[8] = {__float2half_rn(a0), __float2half_rn(a1),
                   __float2half_rn(a2), __float2half_rn(a3),
                   __float2half_rn(a4), __float2half_rn(a5),
                   __float2half_rn(a6), __float2half_rn(a7)};
    *(uint4*)(dst + (size_t)row * 256 + lane * 8) = *(uint4*)o;
}

// ---------------- weight prep: W1-3 transpose + W4 padded ----------------
__global__ void prep_w_f16(const float* __restrict__ W1, const float* __restrict__ W2,
                           const float* __restrict__ W3, const float* __restrict__ W4,
                           __half* __restrict__ Bh, __half* __restrict__ W4p) {
    int n = blockIdx.x;
    int k = threadIdx.x;
    int l = blockIdx.y;
    if (l < 3) {
        const float* W = (l == 0) ? W1 : (l == 1) ? W2 : W3;
        Bh[(size_t)l * NF * NF + (size_t)n * NF + k] = __float2half_rn(W[(size_t)k * NF + n]);
    } else if (n < 64) {
        W4p[(size_t)n * NF + k] = (n < 40) ? __float2half_rn(W4[(size_t)k * 40 + n])
                                           : __ushort_as_half((unsigned short)0);
    }
}

// ---------------- shared tile layout ----------------
#define PITCH 72
#define A_SZ1 (128 * PITCH * 2)          // 18432
#define B_SZ1 (256 * PITCH * 2)          // 36864
#define STAGE1 (A_SZ1 + B_SZ1)           // 55296
#define FUSED_SMEM (3 * STAGE1)          // 165888
#define H1_PITCH 264
#define H1_OFF 0                         // 128*264*2 = 67584
#define B2_OFF0 68608
#define B2_OFF1 (68608 + 36864)
#define BIAS_OFF (B2_OFF1 + 36864)       // 142336; written only AFTER phase 1

// ---------------- fused GEMM1+GEMM2 ----------------
__global__ void __launch_bounds__(512) fused_mlp2_kernel(
    const __half* __restrict__ Ah, const __half* __restrict__ W1h,
    const float* __restrict__ b1, const __half* __restrict__ W2h,
    const float* __restrict__ b2, __half* __restrict__ Out, int M) {
    extern __shared__ char smem[];
    uint32_t sbase = smem_u32(smem);
    uint32_t sh1 = sbase + H1_OFF;

    int tid = threadIdx.x, lane = tid & 31, wid = tid >> 5;
    int m0 = blockIdx.x * 128;
    int wm = (wid >> 2) * 32;
    int wn = (wid & 3) * 64;

    int arow = tid >> 2, aq = tid & 3;
    int gmA = m0 + arow; if (gmA >= M) gmA = M - 1;
    int brow = tid >> 1, bh = tid & 1;

    float acc[2][8][4];
#pragma unroll
    for (int i = 0; i < 2; i++)
#pragma unroll
        for (int j = 0; j < 8; j++)
#pragma unroll
            for (int q = 0; q < 4; q++) acc[i][j][q] = 0.f;

    auto issue1 = [&](int it, int stg) {
        uint32_t sA = sbase + stg * STAGE1;
        uint32_t sB = sA + A_SZ1;
        const __half* asrc = Ah + (size_t)gmA * NF + it * 64 + aq * 16;
        uint32_t adst = sA + (uint32_t)(arow * PITCH + aq * 16) * 2;
        CP_ASYNC16(adst, asrc);
        CP_ASYNC16(adst + 16, asrc + 8);
        const __half* bsrc = W1h + (size_t)brow * NF + it * 64 + bh * 32;
        uint32_t bdst = sB + (uint32_t)(brow * PITCH + bh * 32) * 2;
#pragma unroll
        for (int j = 0; j < 4; j++) CP_ASYNC16(bdst + j * 16, bsrc + j * 8);
        CP_COMMIT();
    };

    auto compute1 = [&](int stg) {
        uint32_t sA = sbase + stg * STAGE1;
        uint32_t sB = sA + A_SZ1;
#pragma unroll
        for (int ks = 0; ks < 4; ks++) {
            uint32_t af[2][4];
#pragma unroll
            for (int mt = 0; mt < 2; mt++) {
                uint32_t addr = sA +
                    (uint32_t)((wm + mt * 16 + (lane & 15)) * PITCH + ks * 16 +
                               ((lane >> 4) << 3)) * 2;
                LDSM_X4(af[mt][0], af[mt][1], af[mt][2], af[mt][3], addr);
            }
            uint32_t bf[4][4];
#pragma unroll
            for (int p = 0; p < 4; p++) {
                uint32_t addr = sB +
                    (uint32_t)((wn + p * 16 + ((lane >> 4) << 3) + (lane & 7)) * PITCH +
                               ks * 16 + ((lane >> 3) & 1) * 8) * 2;
                LDSM_X4(bf[p][0], bf[p][1], bf[p][2], bf[p][3], addr);
            }
#pragma unroll
            for (int mt = 0; mt < 2; mt++)
#pragma unroll
                for (int nt = 0; nt < 8; nt++)
                    mma_f16(acc[mt][nt], af[mt], &bf[nt >> 1][(nt & 1) * 2]);
        }
    };

    issue1(0, 0);
    issue1(1, 1);
    for (int it = 0; it < 4; it++) {
        if (it < 3) CP_WAIT1(); else CP_WAIT0();
        __syncthreads();
        compute1(it % 3);
        if (it + 2 < 4) issue1(it + 2, (it + 2) % 3);
    }
    __syncthreads();

    // h1 = relu(acc + b1) -> smem; reset acc
#pragma unroll
    for (int mt = 0; mt < 2; mt++) {
        int r0 = wm + mt * 16 + (lane >> 2);
#pragma unroll
        for (int nt = 0; nt < 8; nt++) {
            int n = wn + nt * 8 + (lane & 3) * 2;
            float c0 = __ldg(b1 + n), c1 = __ldg(b1 + n + 1);
#pragma unroll
            for (int h = 0; h < 2; h++) {
                int r = r0 + h * 8;
                __half ph[2] = {
                    __float2half_rn(fmaxf(acc[mt][nt][h * 2 + 0] + c0, 0.f)),
                    __float2half_rn(fmaxf(acc[mt][nt][h * 2 + 1] + c1, 0.f))};
                asm volatile("st.shared.b32 [%0], %1;"
                             :: "r"(sh1 + (uint32_t)(r * H1_PITCH + n) * 2),
                                "r"(*(uint32_t*)ph));
                acc[mt][nt][h * 2 + 0] = 0.f;
                acc[mt][nt][h * 2 + 1] = 0.f;
            }
        }
    }
    __syncthreads();

    // phase 2: h1(smem) @ W2
    uint32_t sB2[2] = {sbase + B2_OFF0, sbase + B2_OFF1};

    auto issue2 = [&](int kc, int buf) {
        const __half* bsrc = W2h + (size_t)brow * NF + kc * 64 + bh * 32;
        uint32_t bdst = sB2[buf] + (uint32_t)(brow * PITCH + bh * 32) * 2;
#pragma unroll
        for (int j = 0; j < 4; j++) CP_ASYNC16(bdst + j * 16, bsrc + j * 8);
        CP_COMMIT();
    };

    auto compute2 = [&](int kc, int buf) {
        uint32_t sB = sB2[buf];
#pragma unroll
        for (int ks = 0; ks < 4; ks++) {
            uint32_t af[2][4];
#pragma unroll
            for (int mt = 0; mt < 2; mt++) {
                uint32_t addr = sh1 +
                    (uint32_t)((wm + mt * 16 + (lane & 15)) * H1_PITCH + kc * 64 +
                               ks * 16 + ((lane >> 4) << 3)) * 2;
                LDSM_X4(af[mt][0], af[mt][1], af[mt][2], af[mt][3], addr);
            }
            uint32_t bf[4][4];
#pragma unroll
            for (int p = 0; p < 4; p++) {
                uint32_t addr = sB +
                    (uint32_t)((wn + p * 16 + ((lane >> 4) << 3) + (lane & 7)) * PITCH +
                               ks * 16 + ((lane >> 3) & 1) * 8) * 2;
                LDSM_X4(bf[p][0], bf[p][1], bf[p][2], bf[p][3], addr);
            }
#pragma unroll
            for (int mt = 0; mt < 2; mt++)
#pragma unroll
                for (int nt = 0; nt < 8; nt++)
                    mma_f16(acc[mt][nt], af[mt], &bf[nt >> 1][(nt & 1) * 2]);
        }
    };

    issue2(0, 0);
    issue2(1, 1);
    for (int kc = 0; kc < 4; kc++) {
        if (kc < 3) CP_WAIT1(); else CP_WAIT0();
        __syncthreads();
        compute2(kc, kc & 1);
        if (kc + 2 < 4) {
            __syncthreads();
            issue2(kc + 2, kc & 1);
        }
    }

    // epilogue: h2 -> gmem fp16
#pragma unroll
    for (int mt = 0; mt < 2; mt++) {
        int rr[2];
        rr[0] = m0 + wm + mt * 16 + (lane >> 2);
        rr[1] = rr[0] + 8;
#pragma unroll
        for (int nt = 0; nt < 8; nt++) {
            int n = wn + nt * 8 + (lane & 3) * 2;
            float c0 = __ldg(b2 + n), c1 = __ldg(b2 + n + 1);
#pragma unroll
            for (int h = 0; h < 2; h++) {
                int r = rr[h];
                if (r >= M) continue;
                __half ph[2] = {
                    __float2half_rn(fmaxf(acc[mt][nt][h * 2 + 0] + c0, 0.f)),
                    __float2half_rn(fmaxf(acc[mt][nt][h * 2 + 1] + c1, 0.f))};
                *(uint32_t*)(Out + (size_t)r * NF + n) = *(uint32_t*)ph;
            }
        }
    }
}

// ---------------- fused GEMM3 + final GEMM(40) + log_softmax ----------------
__global__ void __launch_bounds__(512) fused_out_kernel(
    const __half* __restrict__ Ah, const __half* __restrict__ W3h,
    const float* __restrict__ b3, const __half* __restrict__ W4p,
    const float* __restrict__ b4, float* __restrict__ Out, int M) {
    extern __shared__ char smem[];
    uint32_t sbase = smem_u32(smem);
    uint32_t sh1 = sbase + H1_OFF;

    int tid = threadIdx.x, lane = tid & 31, wid = tid >> 5;
    int m0 = blockIdx.x * 128;
    int wm = (wid >> 2) * 32;
    int wn = (wid & 3) * 64;

    int arow = tid >> 2, aq = tid & 3;
    int gmA = m0 + arow; if (gmA >= M) gmA = M - 1;
    int brow = tid >> 1, bh = tid & 1;

    float* sbias = (float*)(smem + BIAS_OFF);   // written AFTER phase 1

    float acc[2][8][4];
#pragma unroll
    for (int i = 0; i < 2; i++)
#pragma unroll
        for (int j = 0; j < 8; j++)
#pragma unroll
            for (int q = 0; q < 4; q++) acc[i][j][q] = 0.f;

    auto issue1 = [&](int it, int stg) {
        uint32_t sA = sbase + stg * STAGE1;
        uint32_t sB = sA + A_SZ1;
        const __half* asrc = Ah + (size_t)gmA * NF + it * 64 + aq * 16;
        uint32_t adst = sA + (uint32_t)(arow * PITCH + aq * 16) * 2;
        CP_ASYNC16(adst, asrc);
        CP_ASYNC16(adst + 16, asrc + 8);
        const __half* bsrc = W3h + (size_t)brow * NF + it * 64 + bh * 32;
        uint32_t bdst = sB + (uint32_t)(brow * PITCH + bh * 32) * 2;
#pragma unroll
        for (int j = 0; j < 4; j++) CP_ASYNC16(bdst + j * 16, bsrc + j * 8);
        CP_COMMIT();
    };

    auto compute1 = [&](int stg) {
        uint32_t sA = sbase + stg * STAGE1;
        uint32_t sB = sA + A_SZ1;
#pragma unroll
        for (int ks = 0; ks < 4; ks++) {
            uint32_t af[2][4];
#pragma unroll
            for (int mt = 0; mt < 2; mt++) {
                uint32_t addr = sA +
                    (uint32_t)((wm + mt * 16 + (lane & 15)) * PITCH + ks * 16 +
                               ((lane >> 4) << 3)) * 2;
                LDSM_X4(af[mt][0], af[mt][1], af[mt][2], af[mt][3], addr);
            }
            uint32_t bf[4][4];
#pragma unroll
            for (int p = 0; p < 4; p++) {
                uint32_t addr = sB +
                    (uint32_t)((wn + p * 16 + ((lane >> 4) << 3) + (lane & 7)) * PITCH +
                               ks * 16 + ((lane >> 3) & 1) * 8) * 2;
                LDSM_X4(bf[p][0], bf[p][1], bf[p][2], bf[p][3], addr);
            }
#pragma unroll
            for (int mt = 0; mt < 2; mt++)
#pragma unroll
                for (int nt = 0; nt < 8; nt++)
                    mma_f16(acc[mt][nt], af[mt], &bf[nt >> 1][(nt & 1) * 2]);
        }
    };

    issue1(0, 0);
    issue1(1, 1);
    for (int it = 0; it < 4; it++) {
        if (it < 3) CP_WAIT1(); else CP_WAIT0();
        __syncthreads();
        compute1(it % 3);
        if (it + 2 < 4) issue1(it + 2, (it + 2) % 3);
    }
    __syncthreads();

    // h4 = relu(acc + b3) -> smem; also write padded b4 bias now (stage bufs dead)
    if (tid < 64) sbias[tid] = (tid < 40) ? b4[tid] : -1e30f;
#pragma unroll
    for (int mt = 0; mt < 2; mt++) {
        int r0 = wm + mt * 16 + (lane >> 2);
#pragma unroll
        for (int nt = 0; nt < 8; nt++) {
            int n = wn + nt * 8 + (lane & 3) * 2;
            float c0 = __ldg(b3 + n), c1 = __ldg(b3 + n + 1);
#pragma unroll
            for (int h = 0; h < 2; h++) {
                int r = r0 + h * 8;
                __half ph[2] = {
                    __float2half_rn(fmaxf(acc[mt][nt][h * 2 + 0] + c0, 0.f)),
                    __float2half_rn(fmaxf(acc[mt][nt][h * 2 + 1] + c1, 0.f))};
                asm volatile("st.shared.b32 [%0], %1;"
                             :: "r"(sh1 + (uint32_t)(r * H1_PITCH + n) * 2),
                                "r"(*(uint32_t*)ph));
            }
        }
    }

    // load W4pad [64 rows][256] into B2_OFF0 (4 k-chunks, PITCH layout)
    uint32_t sW4 = sbase + B2_OFF0;
    if (tid < 128) {
        int br = tid >> 1, bq = tid & 1;
#pragma unroll
        for (int kc = 0; kc < 4; kc++) {
            const __half* bsrc = W4p + (size_t)br * NF + kc * 64 + bq * 32;
            uint32_t bdst = sW4 + (uint32_t)(kc * 64 * PITCH + br * PITCH + bq * 32) * 2;
#pragma unroll
            for (int j = 0; j < 4; j++) CP_ASYNC16(bdst + j * 16, bsrc + j * 8);
        }
    }
    CP_COMMIT();
    CP_WAIT0();
    __syncthreads();

    // phase 2: logits = h4(smem) @ W4pad; warps 0..7
    if (wid < 8) {
        float acc2[8][4];
#pragma unroll
        for (int j = 0; j < 8; j++)
#pragma unroll
            for (int q = 0; q < 4; q++) acc2[j][q] = 0.f;

#pragma unroll
        for (int kc = 0; kc < 4; kc++) {
#pragma unroll
            for (int ks = 0; ks < 4; ks++) {
                uint32_t af[4];
                uint32_t aaddr = sh1 +
                    (uint32_t)((wid * 16 + (lane & 15)) * H1_PITCH + kc * 64 +
                               ks * 16 + ((lane >> 4) << 3)) * 2;
                LDSM_X4(af[0], af[1], af[2], af[3], aaddr);
                uint32_t bf[4][4];
#pragma unroll
                for (int p = 0; p < 4; p++) {
                    uint32_t baddr = sW4 +
                        (uint32_t)(kc * 64 * PITCH +
                                   (p * 16 + ((lane >> 4) << 3) + (lane & 7)) * PITCH +
                                   ks * 16 + ((lane >> 3) & 1) * 8) * 2;
                    LDSM_X4(bf[p][0], bf[p][1], bf[p][2], bf[p][3], baddr);
                }
#pragma unroll
                for (int nt = 0; nt < 8; nt++)
                    mma_f16(acc2[nt], af, &bf[nt >> 1][(nt & 1) * 2]);
            }
        }

        // log_softmax: row gr = m0 + wid*16 + (lane>>2) + h*8
#pragma unroll
        for (int h = 0; h < 2; h++) {
            int gr = m0 + wid * 16 + (lane >> 2) + h * 8;
            float lg[16];
            float mx = -1e30f;
#pragma unroll
            for (int nt = 0; nt < 8; nt++) {
                int c = nt * 8 + (lane & 3) * 2;
                lg[nt * 2 + 0] = acc2[nt][h * 2 + 0] + sbias[c];
                lg[nt * 2 + 1] = acc2[nt][h * 2 + 1] + sbias[c + 1];
                mx = fmaxf(mx, fmaxf(lg[nt * 2], lg[nt * 2 + 1]));
            }
            mx = fmaxf(mx, __shfl_xor_sync(0xffffffffu, mx, 1));
            mx = fmaxf(mx, __shfl_xor_sync(0xffffffffu, mx, 2));
            float s = 0.f;
#pragma unroll
            for (int q = 0; q < 16; q++) s += __expf(lg[q] - mx);
            s += __shfl_xor_sync(0xffffffffu, s, 1);
            s += __shfl_xor_sync(0xffffffffu, s, 2);
            float lse = mx + __logf(s);
            if (gr < M) {
#pragma unroll
                for (int nt = 0; nt < 5; nt++) {
                    int c = nt * 8 + (lane & 3) * 2;
                    if (c < 40) {
                        float2 o;
                        o.x = lg[nt * 2 + 0] - lse;
                        o.y = lg[nt * 2 + 1] - lse;
                        *(float2*)(Out + (size_t)gr * 40 + c) = o;
                    }
                }
            }
        }
    }
}

// ---------------- launch ----------------
extern "C" void kernel_launch(void* const* d_in, const int* in_sizes, int n_in,
                              void* d_out, int out_size) {
    const float* x    = (const float*)d_in[0];
    const int*   erow = (const int*)d_in[1];
    const int*   ecol = (const int*)d_in[2];
    const float* ew   = (const float*)d_in[3];
    const float* W1 = (const float*)d_in[4];
    const float* b1 = (const float*)d_in[5];
    const float* W2 = (const float*)d_in[6];
    const float* b2 = (const float*)d_in[7];
    const float* W3 = (const float*)d_in[8];
    const float* b3 = (const float*)d_in[9];
    const float* W4 = (const float*)d_in[10];
    const float* b4 = (const float*)d_in[11];
    float* out = (float*)d_out;

    int E = in_sizes[1];
    int n = in_sizes[0] / NF;

    __half *wh, *h0, *h1, *w4p;
    int* rowptr;
    cudaGetSymbolAddress((void**)&rowptr, g_rowptr);
    cudaGetSymbolAddress((void**)&wh, g_Wh);
    cudaGetSymbolAddress((void**)&h0, g_h0);
    cudaGetSymbolAddress((void**)&h1, g_h1);
    cudaGetSymbolAddress((void**)&w4p, g_W4p);

    cudaFuncSetAttribute(fused_mlp2_kernel,
                         cudaFuncAttributeMaxDynamicSharedMemorySize, FUSED_SMEM);
    cudaFuncSetAttribute(fused_out_kernel,
                         cudaFuncAttributeMaxDynamicSharedMemorySize, FUSED_SMEM);

    int total4 = n * 64;
    int chN = (total4 > E) ? total4 : E;

    // CSR build + x conv
    cudaMemsetAsync(rowptr, 0, (size_t)(n + 1) * sizeof(int));
    conv_hist_kernel<<<(chN / 2 + 255) / 256, 256>>>(x, h0, erow, E, total4);  // 1
    scan_kernel<<<1, 1024>>>(n);                                               // 2
    scatter_kernel<<<(E / 4 + 255) / 256, 256>>>(erow, ecol, ew, E);           // 3

    int spmm_blocks = (n * 32 + 255) / 256;   // one warp per row
    int fgrid = (n + 127) / 128;

    // h0g = x + spmm(x): h0 -> h1                       [4th kernel: profiled]
    spmm_f16_kernel<<<spmm_blocks, 256>>>(h0, h1, n);

    // weight prep (W1-3 transpose + W4 pad)
    dim3 pgrid(256, 4);
    prep_w_f16<<<pgrid, 256>>>(W1, W2, W3, W4, wh, w4p);

    // h2g = relu(relu(h0g@W1+b1)@W2+b2): h1 -> h0
    fused_mlp2_kernel<<<fgrid, 512, FUSED_SMEM>>>(
        h1, wh + 0 * (size_t)NF * NF, b1, wh + 1 * (size_t)NF * NF, b2, h0, n);
    // h3g = h2g + spmm(h2g): h0 -> h1
    spmm_f16_kernel<<<spmm_blocks, 256>>>(h0, h1, n);
    // out = log_softmax(relu(h3g@W3+b3) @ W4 + b4)
    fused_out_kernel<<<fgrid, 512, FUSED_SMEM>>>(
        h1, wh + 2 * (size_t)NF * NF, b3, w4p, b4, out, n);
}

// round 14
// speedup vs baseline: 2.0350x; 1.0173x over previous
#include <cuda_runtime.h>
#include <cuda_fp16.h>
#include <math.h>
#include <stdint.h>

#define NNODES 100000
#define NEDGES 3200000
#define NF 256

// ---------------- scratch (device globals; no allocs allowed) ----------------
__device__ __half g_h0[(size_t)NNODES * NF];            // fp16 ping
__device__ __half g_h1[(size_t)NNODES * NF];            // fp16 pong
__device__ int   g_rowptr[NNODES + 1];
__device__ int   g_cursor[NNODES];
__device__ uint2 g_cw[NEDGES];                          // packed {col*512 (byte off), weight}
__device__ __half g_Wh[3][NF * NF];                     // fp16 weights, [N][K] K-major
__device__ __half g_W4p[64 * NF];                       // W4 padded [64][256] K-major fp16

// ---------------- helpers ----------------
__device__ __forceinline__ uint32_t smem_u32(const void* p) {
    uint32_t a;
    asm("{ .reg .u64 t; cvta.to.shared.u64 t, %1; cvt.u32.u64 %0, t; }" : "=r"(a) : "l"(p));
    return a;
}

#define LDSM_X4(r0, r1, r2, r3, addr) \
    asm volatile("ldmatrix.sync.aligned.m8n8.x4.shared.b16 {%0,%1,%2,%3}, [%4];" \
                 : "=r"(r0), "=r"(r1), "=r"(r2), "=r"(r3) : "r"(addr))

__device__ __forceinline__ void mma_f16(float* d, const uint32_t* a, const uint32_t* b) {
    asm volatile(
        "mma.sync.aligned.m16n8k16.row.col.f32.f16.f16.f32 "
        "{%0,%1,%2,%3}, {%4,%5,%6,%7}, {%8,%9}, {%0,%1,%2,%3};"
        : "+f"(d[0]), "+f"(d[1]), "+f"(d[2]), "+f"(d[3])
        : "r"(a[0]), "r"(a[1]), "r"(a[2]), "r"(a[3]), "r"(b[0]), "r"(b[1]));
}

#define CP_ASYNC16(dst, src) \
    asm volatile("cp.async.cg.shared.global [%0], [%1], 16;" :: "r"(dst), "l"(src))
#define CP_COMMIT() asm volatile("cp.async.commit_group;")
#define CP_WAIT1() asm volatile("cp.async.wait_group 1;")
#define CP_WAIT0() asm volatile("cp.async.wait_group 0;")

// packed f32x2 ops (sm_100-family PTX)
__device__ __forceinline__ uint64_t pack_f32x2(float lo, float hi) {
    uint64_t r;
    asm("mov.b64 %0, {%1, %2};" : "=l"(r) : "f"(lo), "f"(hi));
    return r;
}
__device__ __forceinline__ void unpack_f32x2(uint64_t v, float& lo, float& hi) {
    asm("mov.b64 {%0, %1}, %2;" : "=f"(lo), "=f"(hi) : "l"(v));
}
__device__ __forceinline__ void fma_f32x2(uint64_t& acc, uint64_t a, uint64_t b) {
    asm("fma.rn.f32x2 %0, %1, %2, %0;" : "+l"(acc) : "l"(a), "l"(b));
}

// ---------------- merged: x -> fp16 copy + degree histogram (x2 unroll) ----------------
__global__ void conv_hist_kernel(const float* __restrict__ x, __half* __restrict__ xh,
                                 const int* __restrict__ erow, int E, int total4) {
    int i = (blockIdx.x * blockDim.x + threadIdx.x) * 2;
#pragma unroll
    for (int j = 0; j < 2; j++) {
        int k = i + j;
        if (k < total4) {
            float4 v = ((const float4*)x)[k];
            __half h[4] = {__float2half_rn(v.x), __float2half_rn(v.y),
                           __float2half_rn(v.z), __float2half_rn(v.w)};
            *(uint2*)(xh + (size_t)k * 4) = *(uint2*)h;
        }
        if (k < E) atomicAdd(&g_rowptr[erow[k]], 1);
    }
}

__global__ void scan_kernel(int n) {
    __shared__ int part[1024];
    int t = threadIdx.x;
    int CH = (n + 1023) / 1024;
    int beg = t * CH;
    int end = min(beg + CH, n);
    int s = 0;
    for (int i = beg; i < end; i++) s += g_rowptr[i];
    part[t] = s;
    __syncthreads();
    for (int off = 1; off < 1024; off <<= 1) {
        int v = (t >= off) ? part[t - off] : 0;
        __syncthreads();
        part[t] += v;
        __syncthreads();
    }
    int base = (t == 0) ? 0 : part[t - 1];
    int run = base;
    for (int i = beg; i < end; i++) {
        int c = g_rowptr[i];
        g_rowptr[i] = run;
        g_cursor[i] = run;
        run += c;
    }
    if (t == 1023) g_rowptr[n] = part[1023];
}

// unroll x4: four independent atomic chains per thread
__global__ void scatter_kernel(const int* __restrict__ erow,
                               const int* __restrict__ ecol,
                               const float* __restrict__ ew, int E) {
    int i = (blockIdx.x * blockDim.x + threadIdx.x) * 4;
#pragma unroll
    for (int j = 0; j < 4; j++) {
        if (i + j < E) {
            int r = erow[i + j];
            int pos = atomicAdd(&g_cursor[r], 1);
            uint2 cw;
            cw.x = (uint32_t)ecol[i + j] * 512u;   // premultiplied byte row offset
            cw.y = __float_as_uint(ew[i + j]);
            g_cw[pos] = cw;
        }
    }
}

// ---------------- SPMM: one warp per row, uint4 gathers, f32x2 accumulate ----------------
__global__ void __launch_bounds__(256, 6) spmm_f16_kernel(
    const __half* __restrict__ src, __half* __restrict__ dst, int n) {
    int row = (blockIdx.x * blockDim.x + threadIdx.x) >> 5;
    if (row >= n) return;
    int lane = threadIdx.x & 31;
    uint32_t foff = (uint32_t)lane * 16;   // 16B per lane, warp covers 512B row
    const char* sp = (const char*)src;

    uint4 rv = __ldg((const uint4*)(sp + (size_t)row * 512 + foff));
    float2 q0 = __half22float2(*(__half2*)&rv.x);
    float2 q1 = __half22float2(*(__half2*)&rv.y);
    float2 q2 = __half22float2(*(__half2*)&rv.z);
    float2 q3 = __half22float2(*(__half2*)&rv.w);
    uint64_t A0 = pack_f32x2(q0.x, q0.y);
    uint64_t A1 = pack_f32x2(q1.x, q1.y);
    uint64_t A2 = pack_f32x2(q2.x, q2.y);
    uint64_t A3 = pack_f32x2(q3.x, q3.y);

    int beg = g_rowptr[row], end = g_rowptr[row + 1];
    int e = beg;

    auto acc1 = [&](uint32_t coff, uint32_t wbits) {
        float w = __uint_as_float(wbits);
        uint64_t w2 = pack_f32x2(w, w);
        uint4 v = __ldg((const uint4*)(sp + (size_t)(coff + foff)));
        float2 p0 = __half22float2(*(__half2*)&v.x);
        float2 p1 = __half22float2(*(__half2*)&v.y);
        float2 p2 = __half22float2(*(__half2*)&v.z);
        float2 p3 = __half22float2(*(__half2*)&v.w);
        fma_f32x2(A0, pack_f32x2(p0.x, p0.y), w2);
        fma_f32x2(A1, pack_f32x2(p1.x, p1.y), w2);
        fma_f32x2(A2, pack_f32x2(p2.x, p2.y), w2);
        fma_f32x2(A3, pack_f32x2(p3.x, p3.y), w2);
    };

    if ((e & 1) && e < end) {
        uint2 cw = __ldg(&g_cw[e]);
        acc1(cw.x, cw.y);
        e++;
    }
    const uint4* cw4 = (const uint4*)g_cw;
    for (; e + 8 <= end; e += 8) {
        uint4 c0 = __ldg(&cw4[(e >> 1) + 0]);
        uint4 c1 = __ldg(&cw4[(e >> 1) + 1]);
        uint4 c2 = __ldg(&cw4[(e >> 1) + 2]);
        uint4 c3 = __ldg(&cw4[(e >> 1) + 3]);
        acc1(c0.x, c0.y); acc1(c0.z, c0.w);
        acc1(c1.x, c1.y); acc1(c1.z, c1.w);
        acc1(c2.x, c2.y); acc1(c2.z, c2.w);
        acc1(c3.x, c3.y); acc1(c3.z, c3.w);
    }
    for (; e + 2 <= end; e += 2) {
        uint4 c = __ldg(&cw4[e >> 1]);
        acc1(c.x, c.y); acc1(c.z, c.w);
    }
    if (e < end) {
        uint2 cw = __ldg(&g_cw[e]);
        acc1(cw.x, cw.y);
    }

    float a0, a1, a2, a3, a4, a5, a6, a7;
    unpack_f32x2(A0, a0, a1);
    unpack_f32x2(A1, a2, a3);
    unpack_f32x2(A2, a4, a5);
    unpack_f32x2(A3, a6, a7);
    __half o[8] = {__float2half_rn(a0), __float2half_rn(a1),
                   __float2half_rn(a2), __float2half_rn(a3),
                   __float2half_rn(a4), __float2half_rn(a5),
                   __float2half_rn(a6), __float2half_rn(a7)};
    *(uint4*)(dst + (size_t)row * 256 + lane * 8) = *(uint4*)o;
}

// ---------------- weight prep: W1-3 transpose + W4 padded ----------------
__global__ void prep_w_f16(const float* __restrict__ W1, const float* __restrict__ W2,
                           const float* __restrict__ W3, const float* __restrict__ W4,
                           __half* __restrict__ Bh, __half* __restrict__ W4p) {
    int n = blockIdx.x;
    int k = threadIdx.x;
    int l = blockIdx.y;
    if (l < 3) {
        const float* W = (l == 0) ? W1 : (l == 1) ? W2 : W3;
        Bh[(size_t)l * NF * NF + (size_t)n * NF + k] = __float2half_rn(W[(size_t)k * NF + n]);
    } else if (n < 64) {
        W4p[(size_t)n * NF + k] = (n < 40) ? __float2half_rn(W4[(size_t)k * 40 + n])
                                           : __ushort_as_half((unsigned short)0);
    }
}

// ---------------- shared tile layout ----------------
#define PITCH 72
#define A_SZ1 (128 * PITCH * 2)          // 18432
#define B_SZ1 (256 * PITCH * 2)          // 36864
#define STAGE1 (A_SZ1 + B_SZ1)           // 55296
#define FUSED_SMEM (3 * STAGE1)          // 165888
#define H1_PITCH 264
#define H1_OFF 0                         // 128*264*2 = 67584
#define B2_OFF0 68608
#define B2_OFF1 (68608 + 36864)
#define BIAS_OFF (B2_OFF1 + 36864)       // 142336; written only AFTER phase 1

// ---------------- fused GEMM1+GEMM2 ----------------
__global__ void __launch_bounds__(512) fused_mlp2_kernel(
    const __half* __restrict__ Ah, const __half* __restrict__ W1h,
    const float* __restrict__ b1, const __half* __restrict__ W2h,
    const float* __restrict__ b2, __half* __restrict__ Out, int M) {
    extern __shared__ char smem[];
    uint32_t sbase = smem_u32(smem);
    uint32_t sh1 = sbase + H1_OFF;

    int tid = threadIdx.x, lane = tid & 31, wid = tid >> 5;
    int m0 = blockIdx.x * 128;
    int wm = (wid >> 2) * 32;
    int wn = (wid & 3) * 64;

    int arow = tid >> 2, aq = tid & 3;
    int gmA = m0 + arow; if (gmA >= M) gmA = M - 1;
    int brow = tid >> 1, bh = tid & 1;

    float acc[2][8][4];
#pragma unroll
    for (int i = 0; i < 2; i++)
#pragma unroll
        for (int j = 0; j < 8; j++)
#pragma unroll
            for (int q = 0; q < 4; q++) acc[i][j][q] = 0.f;

    auto issue1 = [&](int it, int stg) {
        uint32_t sA = sbase + stg * STAGE1;
        uint32_t sB = sA + A_SZ1;
        const __half* asrc = Ah + (size_t)gmA * NF + it * 64 + aq * 16;
        uint32_t adst = sA + (uint32_t)(arow * PITCH + aq * 16) * 2;
        CP_ASYNC16(adst, asrc);
        CP_ASYNC16(adst + 16, asrc + 8);
        const __half* bsrc = W1h + (size_t)brow * NF + it * 64 + bh * 32;
        uint32_t bdst = sB + (uint32_t)(brow * PITCH + bh * 32) * 2;
#pragma unroll
        for (int j = 0; j < 4; j++) CP_ASYNC16(bdst + j * 16, bsrc + j * 8);
        CP_COMMIT();
    };

    auto compute1 = [&](int stg) {
        uint32_t sA = sbase + stg * STAGE1;
        uint32_t sB = sA + A_SZ1;
#pragma unroll
        for (int ks = 0; ks < 4; ks++) {
            uint32_t af[2][4];
#pragma unroll
            for (int mt = 0; mt < 2; mt++) {
                uint32_t addr = sA +
                    (uint32_t)((wm + mt * 16 + (lane & 15)) * PITCH + ks * 16 +
                               ((lane >> 4) << 3)) * 2;
                LDSM_X4(af[mt][0], af[mt][1], af[mt][2], af[mt][3], addr);
            }
            uint32_t bf[4][4];
#pragma unroll
            for (int p = 0; p < 4; p++) {
                uint32_t addr = sB +
                    (uint32_t)((wn + p * 16 + ((lane >> 4) << 3) + (lane & 7)) * PITCH +
                               ks * 16 + ((lane >> 3) & 1) * 8) * 2;
                LDSM_X4(bf[p][0], bf[p][1], bf[p][2], bf[p][3], addr);
            }
#pragma unroll
            for (int mt = 0; mt < 2; mt++)
#pragma unroll
                for (int nt = 0; nt < 8; nt++)
                    mma_f16(acc[mt][nt], af[mt], &bf[nt >> 1][(nt & 1) * 2]);
        }
    };

    issue1(0, 0);
    issue1(1, 1);
    for (int it = 0; it < 4; it++) {
        if (it < 3) CP_WAIT1(); else CP_WAIT0();
        __syncthreads();
        compute1(it % 3);
        if (it + 2 < 4) issue1(it + 2, (it + 2) % 3);
    }
    __syncthreads();

    // h1 = relu(acc + b1) -> smem; reset acc
#pragma unroll
    for (int mt = 0; mt < 2; mt++) {
        int r0 = wm + mt * 16 + (lane >> 2);
#pragma unroll
        for (int nt = 0; nt < 8; nt++) {
            int n = wn + nt * 8 + (lane & 3) * 2;
            float c0 = __ldg(b1 + n), c1 = __ldg(b1 + n + 1);
#pragma unroll
            for (int h = 0; h < 2; h++) {
                int r = r0 + h * 8;
                __half ph[2] = {
                    __float2half_rn(fmaxf(acc[mt][nt][h * 2 + 0] + c0, 0.f)),
                    __float2half_rn(fmaxf(acc[mt][nt][h * 2 + 1] + c1, 0.f))};
                asm volatile("st.shared.b32 [%0], %1;"
                             :: "r"(sh1 + (uint32_t)(r * H1_PITCH + n) * 2),
                                "r"(*(uint32_t*)ph));
                acc[mt][nt][h * 2 + 0] = 0.f;
                acc[mt][nt][h * 2 + 1] = 0.f;
            }
        }
    }
    __syncthreads();

    // phase 2: h1(smem) @ W2
    uint32_t sB2[2] = {sbase + B2_OFF0, sbase + B2_OFF1};

    auto issue2 = [&](int kc, int buf) {
        const __half* bsrc = W2h + (size_t)brow * NF + kc * 64 + bh * 32;
        uint32_t bdst = sB2[buf] + (uint32_t)(brow * PITCH + bh * 32) * 2;
#pragma unroll
        for (int j = 0; j < 4; j++) CP_ASYNC16(bdst + j * 16, bsrc + j * 8);
        CP_COMMIT();
    };

    auto compute2 = [&](int kc, int buf) {
        uint32_t sB = sB2[buf];
#pragma unroll
        for (int ks = 0; ks < 4; ks++) {
            uint32_t af[2][4];
#pragma unroll
            for (int mt = 0; mt < 2; mt++) {
                uint32_t addr = sh1 +
                    (uint32_t)((wm + mt * 16 + (lane & 15)) * H1_PITCH + kc * 64 +
                               ks * 16 + ((lane >> 4) << 3)) * 2;
                LDSM_X4(af[mt][0], af[mt][1], af[mt][2], af[mt][3], addr);
            }
            uint32_t bf[4][4];
#pragma unroll
            for (int p = 0; p < 4; p++) {
                uint32_t addr = sB +
                    (uint32_t)((wn + p * 16 + ((lane >> 4) << 3) + (lane & 7)) * PITCH +
                               ks * 16 + ((lane >> 3) & 1) * 8) * 2;
                LDSM_X4(bf[p][0], bf[p][1], bf[p][2], bf[p][3], addr);
            }
#pragma unroll
            for (int mt = 0; mt < 2; mt++)
#pragma unroll
                for (int nt = 0; nt < 8; nt++)
                    mma_f16(acc[mt][nt], af[mt], &bf[nt >> 1][(nt & 1) * 2]);
        }
    };

    issue2(0, 0);
    issue2(1, 1);
    for (int kc = 0; kc < 4; kc++) {
        if (kc < 3) CP_WAIT1(); else CP_WAIT0();
        __syncthreads();
        compute2(kc, kc & 1);
        if (kc + 2 < 4) {
            __syncthreads();
            issue2(kc + 2, kc & 1);
        }
    }

    // epilogue: h2 -> gmem fp16
#pragma unroll
    for (int mt = 0; mt < 2; mt++) {
        int rr[2];
        rr[0] = m0 + wm + mt * 16 + (lane >> 2);
        rr[1] = rr[0] + 8;
#pragma unroll
        for (int nt = 0; nt < 8; nt++) {
            int n = wn + nt * 8 + (lane & 3) * 2;
            float c0 = __ldg(b2 + n), c1 = __ldg(b2 + n + 1);
#pragma unroll
            for (int h = 0; h < 2; h++) {
                int r = rr[h];
                if (r >= M) continue;
                __half ph[2] = {
                    __float2half_rn(fmaxf(acc[mt][nt][h * 2 + 0] + c0, 0.f)),
                    __float2half_rn(fmaxf(acc[mt][nt][h * 2 + 1] + c1, 0.f))};
                *(uint32_t*)(Out + (size_t)r * NF + n) = *(uint32_t*)ph;
            }
        }
    }
}

// ---------------- fused GEMM3 + final GEMM(40) + log_softmax ----------------
__global__ void __launch_bounds__(512) fused_out_kernel(
    const __half* __restrict__ Ah, const __half* __restrict__ W3h,
    const float* __restrict__ b3, const __half* __restrict__ W4p,
    const float* __restrict__ b4, float* __restrict__ Out, int M) {
    extern __shared__ char smem[];
    uint32_t sbase = smem_u32(smem);
    uint32_t sh1 = sbase + H1_OFF;

    int tid = threadIdx.x, lane = tid & 31, wid = tid >> 5;
    int m0 = blockIdx.x * 128;
    int wm = (wid >> 2) * 32;
    int wn = (wid & 3) * 64;

    int arow = tid >> 2, aq = tid & 3;
    int gmA = m0 + arow; if (gmA >= M) gmA = M - 1;
    int brow = tid >> 1, bh = tid & 1;

    float* sbias = (float*)(smem + BIAS_OFF);   // written AFTER phase 1

    float acc[2][8][4];
#pragma unroll
    for (int i = 0; i < 2; i++)
#pragma unroll
        for (int j = 0; j < 8; j++)
#pragma unroll
            for (int q = 0; q < 4; q++) acc[i][j][q] = 0.f;

    auto issue1 = [&](int it, int stg) {
        uint32_t sA = sbase + stg * STAGE1;
        uint32_t sB = sA + A_SZ1;
        const __half* asrc = Ah + (size_t)gmA * NF + it * 64 + aq * 16;
        uint32_t adst = sA + (uint32_t)(arow * PITCH + aq * 16) * 2;
        CP_ASYNC16(adst, asrc);
        CP_ASYNC16(adst + 16, asrc + 8);
        const __half* bsrc = W3h + (size_t)brow * NF + it * 64 + bh * 32;
        uint32_t bdst = sB + (uint32_t)(brow * PITCH + bh * 32) * 2;
#pragma unroll
        for (int j = 0; j < 4; j++) CP_ASYNC16(bdst + j * 16, bsrc + j * 8);
        CP_COMMIT();
    };

    auto compute1 = [&](int stg) {
        uint32_t sA = sbase + stg * STAGE1;
        uint32_t sB = sA + A_SZ1;
#pragma unroll
        for (int ks = 0; ks < 4; ks++) {
            uint32_t af[2][4];
#pragma unroll
            for (int mt = 0; mt < 2; mt++) {
                uint32_t addr = sA +
                    (uint32_t)((wm + mt * 16 + (lane & 15)) * PITCH + ks * 16 +
                               ((lane >> 4) << 3)) * 2;
                LDSM_X4(af[mt][0], af[mt][1], af[mt][2], af[mt][3], addr);
            }
            uint32_t bf[4][4];
#pragma unroll
            for (int p = 0; p < 4; p++) {
                uint32_t addr = sB +
                    (uint32_t)((wn + p * 16 + ((lane >> 4) << 3) + (lane & 7)) * PITCH +
                               ks * 16 + ((lane >> 3) & 1) * 8) * 2;
                LDSM_X4(bf[p][0], bf[p][1], bf[p][2], bf[p][3], addr);
            }
#pragma unroll
            for (int mt = 0; mt < 2; mt++)
#pragma unroll
                for (int nt = 0; nt < 8; nt++)
                    mma_f16(acc[mt][nt], af[mt], &bf[nt >> 1][(nt & 1) * 2]);
        }
    };

    issue1(0, 0);
    issue1(1, 1);
    for (int it = 0; it < 4; it++) {
        if (it < 3) CP_WAIT1(); else CP_WAIT0();
        __syncthreads();
        compute1(it % 3);
        if (it + 2 < 4) issue1(it + 2, (it + 2) % 3);
    }
    __syncthreads();

    // h4 = relu(acc + b3) -> smem; also write padded b4 bias now (stage bufs dead)
    if (tid < 64) sbias[tid] = (tid < 40) ? b4[tid] : -1e30f;
#pragma unroll
    for (int mt = 0; mt < 2; mt++) {
        int r0 = wm + mt * 16 + (lane >> 2);
#pragma unroll
        for (int nt = 0; nt < 8; nt++) {
            int n = wn + nt * 8 + (lane & 3) * 2;
            float c0 = __ldg(b3 + n), c1 = __ldg(b3 + n + 1);
#pragma unroll
            for (int h = 0; h < 2; h++) {
                int r = r0 + h * 8;
                __half ph[2] = {
                    __float2half_rn(fmaxf(acc[mt][nt][h * 2 + 0] + c0, 0.f)),
                    __float2half_rn(fmaxf(acc[mt][nt][h * 2 + 1] + c1, 0.f))};
                asm volatile("st.shared.b32 [%0], %1;"
                             :: "r"(sh1 + (uint32_t)(r * H1_PITCH + n) * 2),
                                "r"(*(uint32_t*)ph));
            }
        }
    }

    // load W4pad [64 rows][256] into B2_OFF0 (4 k-chunks, PITCH layout)
    uint32_t sW4 = sbase + B2_OFF0;
    if (tid < 128) {
        int br = tid >> 1, bq = tid & 1;
#pragma unroll
        for (int kc = 0; kc < 4; kc++) {
            const __half* bsrc = W4p + (size_t)br * NF + kc * 64 + bq * 32;
            uint32_t bdst = sW4 + (uint32_t)(kc * 64 * PITCH + br * PITCH + bq * 32) * 2;
#pragma unroll
            for (int j = 0; j < 4; j++) CP_ASYNC16(bdst + j * 16, bsrc + j * 8);
        }
    }
    CP_COMMIT();
    CP_WAIT0();
    __syncthreads();

    // phase 2: logits = h4(smem) @ W4pad; warps 0..7
    if (wid < 8) {
        float acc2[8][4];
#pragma unroll
        for (int j = 0; j < 8; j++)
#pragma unroll
            for (int q = 0; q < 4; q++) acc2[j][q] = 0.f;

#pragma unroll
        for (int kc = 0; kc < 4; kc++) {
#pragma unroll
            for (int ks = 0; ks < 4; ks++) {
                uint32_t af[4];
                uint32_t aaddr = sh1 +
                    (uint32_t)((wid * 16 + (lane & 15)) * H1_PITCH + kc * 64 +
                               ks * 16 + ((lane >> 4) << 3)) * 2;
                LDSM_X4(af[0], af[1], af[2], af[3], aaddr);
                uint32_t bf[4][4];
#pragma unroll
                for (int p = 0; p < 4; p++) {
                    uint32_t baddr = sW4 +
                        (uint32_t)(kc * 64 * PITCH +
                                   (p * 16 + ((lane >> 4) << 3) + (lane & 7)) * PITCH +
                                   ks * 16 + ((lane >> 3) & 1) * 8) * 2;
                    LDSM_X4(bf[p][0], bf[p][1], bf[p][2], bf[p][3], baddr);
                }
#pragma unroll
                for (int nt = 0; nt < 8; nt++)
                    mma_f16(acc2[nt], af, &bf[nt >> 1][(nt & 1) * 2]);
            }
        }

        // log_softmax: row gr = m0 + wid*16 + (lane>>2) + h*8
#pragma unroll
        for (int h = 0; h < 2; h++) {
            int gr = m0 + wid * 16 + (lane >> 2) + h * 8;
            float lg[16];
            float mx = -1e30f;
#pragma unroll
            for (int nt = 0; nt < 8; nt++) {
                int c = nt * 8 + (lane & 3) * 2;
                lg[nt * 2 + 0] = acc2[nt][h * 2 + 0] + sbias[c];
                lg[nt * 2 + 1] = acc2[nt][h * 2 + 1] + sbias[c + 1];
                mx = fmaxf(mx, fmaxf(lg[nt * 2], lg[nt * 2 + 1]));
            }
            mx = fmaxf(mx, __shfl_xor_sync(0xffffffffu, mx, 1));
            mx = fmaxf(mx, __shfl_xor_sync(0xffffffffu, mx, 2));
            float s = 0.f;
#pragma unroll
            for (int q = 0; q < 16; q++) s += __expf(lg[q] - mx);
            s += __shfl_xor_sync(0xffffffffu, s, 1);
            s += __shfl_xor_sync(0xffffffffu, s, 2);
            float lse = mx + __logf(s);
            if (gr < M) {
#pragma unroll
                for (int nt = 0; nt < 5; nt++) {
                    int c = nt * 8 + (lane & 3) * 2;
                    if (c < 40) {
                        float2 o;
                        o.x = lg[nt * 2 + 0] - lse;
                        o.y = lg[nt * 2 + 1] - lse;
                        *(float2*)(Out + (size_t)gr * 40 + c) = o;
                    }
                }
            }
        }
    }
}

// ---------------- launch ----------------
extern "C" void kernel_launch(void* const* d_in, const int* in_sizes, int n_in,
                              void* d_out, int out_size) {
    const float* x    = (const float*)d_in[0];
    const int*   erow = (const int*)d_in[1];
    const int*   ecol = (const int*)d_in[2];
    const float* ew   = (const float*)d_in[3];
    const float* W1 = (const float*)d_in[4];
    const float* b1 = (const float*)d_in[5];
    const float* W2 = (const float*)d_in[6];
    const float* b2 = (const float*)d_in[7];
    const float* W3 = (const float*)d_in[8];
    const float* b3 = (const float*)d_in[9];
    const float* W4 = (const float*)d_in[10];
    const float* b4 = (const float*)d_in[11];
    float* out = (float*)d_out;

    int E = in_sizes[1];
    int n = in_sizes[0] / NF;

    __half *wh, *h0, *h1, *w4p;
    int* rowptr;
    cudaGetSymbolAddress((void**)&rowptr, g_rowptr);
    cudaGetSymbolAddress((void**)&wh, g_Wh);
    cudaGetSymbolAddress((void**)&h0, g_h0);
    cudaGetSymbolAddress((void**)&h1, g_h1);
    cudaGetSymbolAddress((void**)&w4p, g_W4p);

    cudaFuncSetAttribute(fused_mlp2_kernel,
                         cudaFuncAttributeMaxDynamicSharedMemorySize, FUSED_SMEM);
    cudaFuncSetAttribute(fused_out_kernel,
                         cudaFuncAttributeMaxDynamicSharedMemorySize, FUSED_SMEM);

    int total4 = n * 64;
    int chN = (total4 > E) ? total4 : E;

    // CSR build + x conv
    cudaMemsetAsync(rowptr, 0, (size_t)(n + 1) * sizeof(int));
    conv_hist_kernel<<<(chN / 2 + 255) / 256, 256>>>(x, h0, erow, E, total4);  // 1
    scan_kernel<<<1, 1024>>>(n);                                               // 2
    scatter_kernel<<<(E / 4 + 255) / 256, 256>>>(erow, ecol, ew, E);           // 3

    int spmm_blocks = (n * 32 + 255) / 256;   // one warp per row
    int fgrid = (n + 127) / 128;

    // h0g = x + spmm(x): h0 -> h1                       [4th kernel: profiled]
    spmm_f16_kernel<<<spmm_blocks, 256>>>(h0, h1, n);

    // weight prep (W1-3 transpose + W4 pad)
    dim3 pgrid(256, 4);
    prep_w_f16<<<pgrid, 256>>>(W1, W2, W3, W4, wh, w4p);

    // h2g = relu(relu(h0g@W1+b1)@W2+b2): h1 -> h0
    fused_mlp2_kernel<<<fgrid, 512, FUSED_SMEM>>>(
        h1, wh + 0 * (size_t)NF * NF, b1, wh + 1 * (size_t)NF * NF, b2, h0, n);
    // h3g = h2g + spmm(h2g): h0 -> h1
    spmm_f16_kernel<<<spmm_blocks, 256>>>(h0, h1, n);
    // out = log_softmax(relu(h3g@W3+b3) @ W4 + b4)
    fused_out_kernel<<<fgrid, 512, FUSED_SMEM>>>(
        h1, wh + 2 * (size_t)NF * NF, b3, w4p, b4, out, n);
}